// round 1
// baseline (speedup 1.0000x reference)
#include <cuda_runtime.h>
#include <cstdint>

#define NN 50000
#define DD 128
#define EE 800000
#define CC 40

// Scratch (no allocations allowed -> device globals)
__device__ float g_agg[NN * DD];
__device__ float g_h1[NN * DD];
__device__ float g_h2[NN * DD];
__device__ float g_deg[NN];
__device__ float g_dinv[NN];

// ---------------------------------------------------------------------------
// Degree computation
// ---------------------------------------------------------------------------
__global__ void deg_kernel(const int* __restrict__ dst, float* __restrict__ deg) {
    int i = blockIdx.x * blockDim.x + threadIdx.x;
    if (i < EE) atomicAdd(&deg[dst[i]], 1.0f);
}

__global__ void dinv_kernel(const float* __restrict__ deg, float* __restrict__ dinv) {
    int i = blockIdx.x * blockDim.x + threadIdx.x;
    if (i < NN) {
        float d = deg[i];
        dinv[i] = d > 0.f ? 1.f / d : 0.f;
    }
}

// ---------------------------------------------------------------------------
// Aggregation: warp per edge, vector reduction (red.global.add.v4.f32)
// agg[dst] += h[src] * mask[e]
// ---------------------------------------------------------------------------
__global__ void agg_kernel(const float* __restrict__ x, const int* __restrict__ src,
                           const int* __restrict__ dst, const float* __restrict__ mask,
                           float* __restrict__ agg) {
    int gid = blockIdx.x * blockDim.x + threadIdx.x;
    int e = gid >> 5;
    int lane = gid & 31;
    if (e >= EE) return;
    int s = src[e];
    int d = dst[e];
    float m = mask[e];
    float4 v = *(const float4*)(x + (size_t)s * DD + lane * 4);
    v.x *= m; v.y *= m; v.z *= m; v.w *= m;
    float* p = agg + (size_t)d * DD + lane * 4;
    asm volatile("red.global.add.v4.f32 [%0], {%1,%2,%3,%4};"
                 :: "l"(p), "f"(v.x), "f"(v.y), "f"(v.z), "f"(v.w)
                 : "memory");
}

// ---------------------------------------------------------------------------
// GIN layer GEMM + BN + ReLU:
//   xin = X + AGG * dinv (row-scaled)
//   OUT = relu( (xin @ W) * S + T ),  S = g*rsqrt(rv+eps), T = (b-rm)*S + beta
// BM=64, BN=128 (full), BK=32, 256 threads, each thread 4x8 outputs.
// ---------------------------------------------------------------------------
__global__ __launch_bounds__(256) void gin_gemm(
    const float* __restrict__ X, const float* __restrict__ AGG,
    const float* __restrict__ dinv, const float* __restrict__ W,
    const float* __restrict__ bias, const float* __restrict__ gam,
    const float* __restrict__ bet, const float* __restrict__ rmean,
    const float* __restrict__ rvar, float* __restrict__ OUT) {
    __shared__ float As[64][33];   // [m][k]
    __shared__ float Bs[32][128];  // [k][n]
    __shared__ float Ssh[128], Tsh[128];

    const int tid = threadIdx.x;
    const int m0 = blockIdx.x * 64;

    if (tid < 128) {
        float s = gam[tid] * rsqrtf(rvar[tid] + 1e-5f);
        Ssh[tid] = s;
        Tsh[tid] = (bias[tid] - rmean[tid]) * s + bet[tid];
    }

    float acc[4][8];
#pragma unroll
    for (int i = 0; i < 4; i++)
#pragma unroll
        for (int j = 0; j < 8; j++) acc[i][j] = 0.f;

    const int tRow = tid >> 4;        // 0..15 (x4 rows)
    const int tCol = tid & 15;        // 0..15 (x8 cols)
    const int lr = tid >> 3;          // A-load row 0..31
    const int lc = (tid & 7) * 4;     // A-load col

    for (int k0 = 0; k0 < 128; k0 += 32) {
        __syncthreads();
        // Load A tile (compute xin on the fly)
#pragma unroll
        for (int p = 0; p < 2; p++) {
            int row = p * 32 + lr;
            int gr = m0 + row;
            float4 v = {0.f, 0.f, 0.f, 0.f};
            if (gr < NN) {
                float4 xv = *(const float4*)(X + (size_t)gr * DD + k0 + lc);
                float4 av = *(const float4*)(AGG + (size_t)gr * DD + k0 + lc);
                float di = dinv[gr];
                v.x = fmaf(av.x, di, xv.x);
                v.y = fmaf(av.y, di, xv.y);
                v.z = fmaf(av.z, di, xv.z);
                v.w = fmaf(av.w, di, xv.w);
            }
            As[row][lc + 0] = v.x;
            As[row][lc + 1] = v.y;
            As[row][lc + 2] = v.z;
            As[row][lc + 3] = v.w;
        }
        // Load B tile
#pragma unroll
        for (int q = 0; q < 4; q++) {
            int f = q * 256 + tid;     // float4 index in 32x128 tile
            int row = f >> 5;
            int c4 = (f & 31) * 4;
            *(float4*)&Bs[row][c4] = *(const float4*)(W + (size_t)(k0 + row) * DD + c4);
        }
        __syncthreads();
#pragma unroll
        for (int k = 0; k < 32; k++) {
            float a0 = As[tRow * 4 + 0][k];
            float a1 = As[tRow * 4 + 1][k];
            float a2 = As[tRow * 4 + 2][k];
            float a3 = As[tRow * 4 + 3][k];
            float4 b0 = *(float4*)&Bs[k][tCol * 8];
            float4 b1 = *(float4*)&Bs[k][tCol * 8 + 4];
            acc[0][0] = fmaf(a0, b0.x, acc[0][0]);
            acc[0][1] = fmaf(a0, b0.y, acc[0][1]);
            acc[0][2] = fmaf(a0, b0.z, acc[0][2]);
            acc[0][3] = fmaf(a0, b0.w, acc[0][3]);
            acc[0][4] = fmaf(a0, b1.x, acc[0][4]);
            acc[0][5] = fmaf(a0, b1.y, acc[0][5]);
            acc[0][6] = fmaf(a0, b1.z, acc[0][6]);
            acc[0][7] = fmaf(a0, b1.w, acc[0][7]);
            acc[1][0] = fmaf(a1, b0.x, acc[1][0]);
            acc[1][1] = fmaf(a1, b0.y, acc[1][1]);
            acc[1][2] = fmaf(a1, b0.z, acc[1][2]);
            acc[1][3] = fmaf(a1, b0.w, acc[1][3]);
            acc[1][4] = fmaf(a1, b1.x, acc[1][4]);
            acc[1][5] = fmaf(a1, b1.y, acc[1][5]);
            acc[1][6] = fmaf(a1, b1.z, acc[1][6]);
            acc[1][7] = fmaf(a1, b1.w, acc[1][7]);
            acc[2][0] = fmaf(a2, b0.x, acc[2][0]);
            acc[2][1] = fmaf(a2, b0.y, acc[2][1]);
            acc[2][2] = fmaf(a2, b0.z, acc[2][2]);
            acc[2][3] = fmaf(a2, b0.w, acc[2][3]);
            acc[2][4] = fmaf(a2, b1.x, acc[2][4]);
            acc[2][5] = fmaf(a2, b1.y, acc[2][5]);
            acc[2][6] = fmaf(a2, b1.z, acc[2][6]);
            acc[2][7] = fmaf(a2, b1.w, acc[2][7]);
            acc[3][0] = fmaf(a3, b0.x, acc[3][0]);
            acc[3][1] = fmaf(a3, b0.y, acc[3][1]);
            acc[3][2] = fmaf(a3, b0.z, acc[3][2]);
            acc[3][3] = fmaf(a3, b0.w, acc[3][3]);
            acc[3][4] = fmaf(a3, b1.x, acc[3][4]);
            acc[3][5] = fmaf(a3, b1.y, acc[3][5]);
            acc[3][6] = fmaf(a3, b1.z, acc[3][6]);
            acc[3][7] = fmaf(a3, b1.w, acc[3][7]);
        }
    }
    // Epilogue: BN + ReLU, vectorized stores
#pragma unroll
    for (int i = 0; i < 4; i++) {
        int gr = m0 + tRow * 4 + i;
        if (gr >= NN) continue;
#pragma unroll
        for (int jj = 0; jj < 2; jj++) {
            int c = tCol * 8 + jj * 4;
            float4 o;
            o.x = fmaxf(fmaf(acc[i][jj * 4 + 0], Ssh[c + 0], Tsh[c + 0]), 0.f);
            o.y = fmaxf(fmaf(acc[i][jj * 4 + 1], Ssh[c + 1], Tsh[c + 1]), 0.f);
            o.z = fmaxf(fmaf(acc[i][jj * 4 + 2], Ssh[c + 2], Tsh[c + 2]), 0.f);
            o.w = fmaxf(fmaf(acc[i][jj * 4 + 3], Ssh[c + 3], Tsh[c + 3]), 0.f);
            *(float4*)(OUT + (size_t)gr * DD + c) = o;
        }
    }
}

// ---------------------------------------------------------------------------
// Final fused kernel: out = 0.5 * ( (h2 @ wp + bp) + relu(BN((h2+agg*dinv) @ w2 + b2)) )
// BM=64, 256 threads. Half the column-threads compute the wp path (A = h2),
// half compute the w2 GIN path (A = xin). Combined through a shared tile.
// ---------------------------------------------------------------------------
__global__ __launch_bounds__(256) void final_kernel(
    const float* __restrict__ H2, const float* __restrict__ AGG,
    const float* __restrict__ dinv,
    const float* __restrict__ W2, const float* __restrict__ b2,
    const float* __restrict__ g2, const float* __restrict__ be2,
    const float* __restrict__ rm2, const float* __restrict__ rv2,
    const float* __restrict__ WP, const float* __restrict__ bp,
    float* __restrict__ OUT) {
    __shared__ float Ah[64][33];   // h2 tile [m][k]
    __shared__ float Ax[64][33];   // xin tile [m][k]
    __shared__ float Bws[32][41];  // WP tile [k][c]
    __shared__ float B2s[32][41];  // W2 tile [k][c]
    __shared__ float zsh[64][40];  // wp-path partial
    __shared__ float S2sh[40], T2sh[40], bpsh[40];

    const int tid = threadIdx.x;
    const int m0 = blockIdx.x * 64;

    if (tid < 40) {
        float s = g2[tid] * rsqrtf(rv2[tid] + 1e-5f);
        S2sh[tid] = s;
        T2sh[tid] = (b2[tid] - rm2[tid]) * s + be2[tid];
        bpsh[tid] = bp[tid];
    }

    float acc[4][5];
#pragma unroll
    for (int i = 0; i < 4; i++)
#pragma unroll
        for (int j = 0; j < 5; j++) acc[i][j] = 0.f;

    const int tRow = tid >> 4;            // 0..15 (x4 rows)
    const int tc = tid & 15;
    const bool pathW2 = (tc >= 8);
    const int cbase = (tc & 7) * 5;       // 8 groups x 5 cols = 40
    const int lr = tid >> 3;
    const int lc = (tid & 7) * 4;

    const float(*Apt)[33];
    const float(*Bpt)[41];

    for (int k0 = 0; k0 < 128; k0 += 32) {
        __syncthreads();
#pragma unroll
        for (int p = 0; p < 2; p++) {
            int row = p * 32 + lr;
            int gr = m0 + row;
            float4 hv = {0.f, 0.f, 0.f, 0.f};
            float4 xv = {0.f, 0.f, 0.f, 0.f};
            if (gr < NN) {
                hv = *(const float4*)(H2 + (size_t)gr * DD + k0 + lc);
                float4 av = *(const float4*)(AGG + (size_t)gr * DD + k0 + lc);
                float di = dinv[gr];
                xv.x = fmaf(av.x, di, hv.x);
                xv.y = fmaf(av.y, di, hv.y);
                xv.z = fmaf(av.z, di, hv.z);
                xv.w = fmaf(av.w, di, hv.w);
            }
            Ah[row][lc + 0] = hv.x; Ah[row][lc + 1] = hv.y;
            Ah[row][lc + 2] = hv.z; Ah[row][lc + 3] = hv.w;
            Ax[row][lc + 0] = xv.x; Ax[row][lc + 1] = xv.y;
            Ax[row][lc + 2] = xv.z; Ax[row][lc + 3] = xv.w;
        }
        for (int idx = tid; idx < 32 * 40; idx += 256) {
            int row = idx / 40;
            int c = idx - row * 40;
            Bws[row][c] = WP[(size_t)(k0 + row) * CC + c];
            B2s[row][c] = W2[(size_t)(k0 + row) * CC + c];
        }
        __syncthreads();

        Apt = pathW2 ? Ax : Ah;
        Bpt = pathW2 ? B2s : Bws;
#pragma unroll
        for (int k = 0; k < 32; k++) {
            float a[4];
#pragma unroll
            for (int i = 0; i < 4; i++) a[i] = Apt[tRow * 4 + i][k];
#pragma unroll
            for (int j = 0; j < 5; j++) {
                float bv = Bpt[k][cbase + j];
#pragma unroll
                for (int i = 0; i < 4; i++) acc[i][j] = fmaf(a[i], bv, acc[i][j]);
            }
        }
    }

    if (!pathW2) {
#pragma unroll
        for (int i = 0; i < 4; i++)
#pragma unroll
            for (int j = 0; j < 5; j++)
                zsh[tRow * 4 + i][cbase + j] = acc[i][j] + bpsh[cbase + j];
    }
    __syncthreads();
    if (pathW2) {
#pragma unroll
        for (int i = 0; i < 4; i++) {
            int gr = m0 + tRow * 4 + i;
            if (gr >= NN) continue;
#pragma unroll
            for (int j = 0; j < 5; j++) {
                int c = cbase + j;
                float h3 = fmaxf(fmaf(acc[i][j], S2sh[c], T2sh[c]), 0.f);
                OUT[(size_t)gr * CC + c] = 0.5f * (zsh[tRow * 4 + i][c] + h3);
            }
        }
    }
}

// ---------------------------------------------------------------------------
extern "C" void kernel_launch(void* const* d_in, const int* in_sizes, int n_in,
                              void* d_out, int out_size) {
    const float* h    = (const float*)d_in[0];
    const int*   esrc = (const int*)d_in[1];
    const int*   edst = (const int*)d_in[2];
    const float* mask = (const float*)d_in[3];
    const float* w0 = (const float*)d_in[4];
    const float* b0 = (const float*)d_in[5];
    const float* g0 = (const float*)d_in[6];
    const float* be0 = (const float*)d_in[7];
    const float* rm0 = (const float*)d_in[8];
    const float* rv0 = (const float*)d_in[9];
    const float* w1 = (const float*)d_in[10];
    const float* b1 = (const float*)d_in[11];
    const float* g1 = (const float*)d_in[12];
    const float* be1 = (const float*)d_in[13];
    const float* rm1 = (const float*)d_in[14];
    const float* rv1 = (const float*)d_in[15];
    const float* w2 = (const float*)d_in[16];
    const float* b2 = (const float*)d_in[17];
    const float* g2 = (const float*)d_in[18];
    const float* be2 = (const float*)d_in[19];
    const float* rm2 = (const float*)d_in[20];
    const float* rv2 = (const float*)d_in[21];
    const float* wp = (const float*)d_in[22];
    const float* bp = (const float*)d_in[23];
    float* out = (float*)d_out;

    float *agg, *h1b, *h2b, *deg, *dinv;
    cudaGetSymbolAddress((void**)&agg, g_agg);
    cudaGetSymbolAddress((void**)&h1b, g_h1);
    cudaGetSymbolAddress((void**)&h2b, g_h2);
    cudaGetSymbolAddress((void**)&deg, g_deg);
    cudaGetSymbolAddress((void**)&dinv, g_dinv);

    const int gemmBlocks = (NN + 63) / 64;
    const int aggBlocks = (EE * 32) / 256;  // warp per edge

    cudaMemsetAsync(deg, 0, NN * sizeof(float));
    cudaMemsetAsync(agg, 0, (size_t)NN * DD * sizeof(float));
    deg_kernel<<<(EE + 255) / 256, 256>>>(edst, deg);
    dinv_kernel<<<(NN + 255) / 256, 256>>>(deg, dinv);

    // Layer 0
    agg_kernel<<<aggBlocks, 256>>>(h, esrc, edst, mask, agg);
    gin_gemm<<<gemmBlocks, 256>>>(h, agg, dinv, w0, b0, g0, be0, rm0, rv0, h1b);

    // Layer 1
    cudaMemsetAsync(agg, 0, (size_t)NN * DD * sizeof(float));
    agg_kernel<<<aggBlocks, 256>>>(h1b, esrc, edst, mask, agg);
    gin_gemm<<<gemmBlocks, 256>>>(h1b, agg, dinv, w1, b1, g1, be1, rm1, rv1, h2b);

    // Layer 2 aggregation + fused final
    cudaMemsetAsync(agg, 0, (size_t)NN * DD * sizeof(float));
    agg_kernel<<<aggBlocks, 256>>>(h2b, esrc, edst, mask, agg);
    final_kernel<<<gemmBlocks, 256>>>(h2b, agg, dinv, w2, b2, g2, be2, rm2, rv2,
                                      wp, bp, out);
}

// round 2
// speedup vs baseline: 1.2887x; 1.2887x over previous
#include <cuda_runtime.h>
#include <cstdint>

#define NN 50000
#define DD 128
#define EE 800000
#define CC 40
#define NB 49   // ceil(NN/1024)

// Scratch (no allocations allowed -> device globals)
__device__ float g_xin[NN * DD];
__device__ float g_h1[NN * DD];
__device__ float g_h2[NN * DD];
__device__ float g_xin2[NN * DD];
__device__ float g_dinv[NN];
__device__ int   g_cnt[NN];
__device__ int   g_cursor[NN];
__device__ int   g_rowptr[NN + 1];
__device__ int   g_bsum[64];
__device__ int   g_csrc[EE];
__device__ float g_cm[EE];

// ---------------------------------------------------------------------------
// CSR build
// ---------------------------------------------------------------------------
__global__ void count_kernel(const int* __restrict__ dst, int* __restrict__ cnt) {
    int i = blockIdx.x * blockDim.x + threadIdx.x;
    if (i < EE) atomicAdd(&cnt[dst[i]], 1);
}

__global__ void blocksum_kernel(const int* __restrict__ cnt, int* __restrict__ bsum) {
    __shared__ int sh[32];
    int tid = threadIdx.x;
    int i = blockIdx.x * 1024 + tid;
    int v = (i < NN) ? cnt[i] : 0;
    int lane = tid & 31, wid = tid >> 5;
#pragma unroll
    for (int o = 16; o > 0; o >>= 1) v += __shfl_down_sync(0xffffffffu, v, o);
    if (lane == 0) sh[wid] = v;
    __syncthreads();
    if (wid == 0) {
        int y = sh[lane];
#pragma unroll
        for (int o = 16; o > 0; o >>= 1) y += __shfl_down_sync(0xffffffffu, y, o);
        if (lane == 0) bsum[blockIdx.x] = y;
    }
}

__global__ void scan_bsum_kernel(int* __restrict__ bsum) {
    if (threadIdx.x == 0) {
        int acc = 0;
        for (int i = 0; i < NB; i++) { int t = bsum[i]; bsum[i] = acc; acc += t; }
    }
}

__global__ void scan_write_kernel(const int* __restrict__ cnt, const int* __restrict__ bsum,
                                  int* __restrict__ rowptr) {
    __shared__ int sh[32];
    int tid = threadIdx.x;
    int b = blockIdx.x;
    int i = b * 1024 + tid;
    int v = (i < NN) ? cnt[i] : 0;
    int lane = tid & 31, wid = tid >> 5;
    int x = v;
#pragma unroll
    for (int o = 1; o < 32; o <<= 1) {
        int t = __shfl_up_sync(0xffffffffu, x, o);
        if (lane >= o) x += t;
    }
    if (lane == 31) sh[wid] = x;
    __syncthreads();
    if (wid == 0) {
        int y = sh[lane];
#pragma unroll
        for (int o = 1; o < 32; o <<= 1) {
            int t = __shfl_up_sync(0xffffffffu, y, o);
            if (lane >= o) y += t;
        }
        sh[lane] = y;
    }
    __syncthreads();
    int incl = x + (wid ? sh[wid - 1] : 0) + bsum[b];
    if (i < NN) rowptr[i + 1] = incl;
    if (b == 0 && tid == 0) rowptr[0] = 0;
}

__global__ void dinv_kernel(const int* __restrict__ cnt, float* __restrict__ dinv) {
    int i = blockIdx.x * blockDim.x + threadIdx.x;
    if (i < NN) {
        int c = cnt[i];
        dinv[i] = c > 0 ? 1.0f / (float)c : 0.0f;
    }
}

__global__ void scatter_kernel(const int* __restrict__ esrc, const int* __restrict__ edst,
                               const float* __restrict__ mask, const int* __restrict__ rowptr,
                               int* __restrict__ cursor, int* __restrict__ csrc,
                               float* __restrict__ cm) {
    int e = blockIdx.x * blockDim.x + threadIdx.x;
    if (e >= EE) return;
    int d = edst[e];
    int pos = atomicAdd(&cursor[d], 1);
    int slot = rowptr[d] + pos;
    csrc[slot] = esrc[e];
    cm[slot] = mask[e];
}

// ---------------------------------------------------------------------------
// CSR aggregation: warp per node. xin = x + dinv * sum(mask * x[src])
// ---------------------------------------------------------------------------
__global__ __launch_bounds__(256) void agg_xin_kernel(
    const float* __restrict__ x, const int* __restrict__ rowptr,
    const int* __restrict__ csrc, const float* __restrict__ cm,
    const float* __restrict__ dinv, float* __restrict__ xin) {
    int g = blockIdx.x * blockDim.x + threadIdx.x;
    int n = g >> 5;
    int lane = g & 31;
    if (n >= NN) return;
    int s = rowptr[n], e = rowptr[n + 1];
    float4 acc = {0.f, 0.f, 0.f, 0.f};
    int i = s;
    for (; i + 1 < e; i += 2) {
        int s0 = __ldg(&csrc[i]);
        int s1 = __ldg(&csrc[i + 1]);
        float m0 = __ldg(&cm[i]);
        float m1 = __ldg(&cm[i + 1]);
        float4 v0 = *(const float4*)(x + (size_t)s0 * DD + lane * 4);
        float4 v1 = *(const float4*)(x + (size_t)s1 * DD + lane * 4);
        acc.x = fmaf(v0.x, m0, acc.x); acc.y = fmaf(v0.y, m0, acc.y);
        acc.z = fmaf(v0.z, m0, acc.z); acc.w = fmaf(v0.w, m0, acc.w);
        acc.x = fmaf(v1.x, m1, acc.x); acc.y = fmaf(v1.y, m1, acc.y);
        acc.z = fmaf(v1.z, m1, acc.z); acc.w = fmaf(v1.w, m1, acc.w);
    }
    if (i < e) {
        int s0 = __ldg(&csrc[i]);
        float m0 = __ldg(&cm[i]);
        float4 v0 = *(const float4*)(x + (size_t)s0 * DD + lane * 4);
        acc.x = fmaf(v0.x, m0, acc.x); acc.y = fmaf(v0.y, m0, acc.y);
        acc.z = fmaf(v0.z, m0, acc.z); acc.w = fmaf(v0.w, m0, acc.w);
    }
    float di = dinv[n];
    float4 xv = *(const float4*)(x + (size_t)n * DD + lane * 4);
    float4 o;
    o.x = fmaf(acc.x, di, xv.x);
    o.y = fmaf(acc.y, di, xv.y);
    o.z = fmaf(acc.z, di, xv.z);
    o.w = fmaf(acc.w, di, xv.w);
    *(float4*)(xin + (size_t)n * DD + lane * 4) = o;
}

// ---------------------------------------------------------------------------
// GIN layer GEMM + BN + ReLU. BM=128, BN=128 (full), BK=32, 256 threads,
// 8x8 per thread (2x2 split of 4x4 for conflict-free B LDS.128).
// OUT = relu( (XIN @ W) * S + T )
// ---------------------------------------------------------------------------
__global__ __launch_bounds__(256) void gin_gemm(
    const float* __restrict__ XIN, const float* __restrict__ W,
    const float* __restrict__ bias, const float* __restrict__ gam,
    const float* __restrict__ bet, const float* __restrict__ rmean,
    const float* __restrict__ rvar, float* __restrict__ OUT) {
    __shared__ float As[128][36];   // [m][k], padded
    __shared__ float Bs[32][132];   // [k][n], padded
    __shared__ float Ssh[128], Tsh[128];

    const int tid = threadIdx.x;
    const int m0 = blockIdx.x * 128;

    if (tid < 128) {
        float s = gam[tid] * rsqrtf(rvar[tid] + 1e-5f);
        Ssh[tid] = s;
        Tsh[tid] = (bias[tid] - rmean[tid]) * s + bet[tid];
    }

    const int tRow = tid >> 4;   // 0..15
    const int tCol = tid & 15;   // 0..15

    float acc[8][8];
#pragma unroll
    for (int i = 0; i < 8; i++)
#pragma unroll
        for (int j = 0; j < 8; j++) acc[i][j] = 0.f;

    // Prefetch registers
    float4 pa[4], pb[4];

    // A load mapping: f = tid + q*256; m = f>>3 (0..127), kk = (f&7)*4
    // B load mapping: f = tid + q*256; r = f>>5 (0..31),  c  = (f&31)*4
#define LOAD_TILE(k0)                                                          \
    {                                                                          \
        _Pragma("unroll") for (int q = 0; q < 4; q++) {                        \
            int f = tid + q * 256;                                             \
            int m = f >> 3;                                                    \
            int kk = (f & 7) * 4;                                              \
            int gr = m0 + m;                                                   \
            pa[q] = (gr < NN) ? *(const float4*)(XIN + (size_t)gr * DD + (k0) + kk) \
                              : make_float4(0.f, 0.f, 0.f, 0.f);               \
            int r = f >> 5;                                                    \
            int c = (f & 31) * 4;                                              \
            pb[q] = *(const float4*)(W + (size_t)((k0) + r) * DD + c);         \
        }                                                                      \
    }

#define STORE_TILE()                                                           \
    {                                                                          \
        _Pragma("unroll") for (int q = 0; q < 4; q++) {                        \
            int f = tid + q * 256;                                             \
            int m = f >> 3;                                                    \
            int kk = (f & 7) * 4;                                              \
            *(float4*)&As[m][kk] = pa[q];                                      \
            int r = f >> 5;                                                    \
            int c = (f & 31) * 4;                                              \
            *(float4*)&Bs[r][c] = pb[q];                                       \
        }                                                                      \
    }

    LOAD_TILE(0);
#pragma unroll
    for (int it = 0; it < 4; it++) {
        __syncthreads();
        STORE_TILE();
        __syncthreads();
        if (it < 3) LOAD_TILE((it + 1) * 32);
#pragma unroll
        for (int k = 0; k < 32; k++) {
            float a[8], b[8];
#pragma unroll
            for (int i = 0; i < 4; i++) {
                a[i] = As[tRow * 4 + i][k];
                a[4 + i] = As[64 + tRow * 4 + i][k];
            }
            float4 b0 = *(float4*)&Bs[k][tCol * 4];
            float4 b1 = *(float4*)&Bs[k][64 + tCol * 4];
            b[0] = b0.x; b[1] = b0.y; b[2] = b0.z; b[3] = b0.w;
            b[4] = b1.x; b[5] = b1.y; b[6] = b1.z; b[7] = b1.w;
#pragma unroll
            for (int i = 0; i < 8; i++)
#pragma unroll
                for (int j = 0; j < 8; j++) acc[i][j] = fmaf(a[i], b[j], acc[i][j]);
        }
    }
#undef LOAD_TILE
#undef STORE_TILE

    // Epilogue: BN + ReLU
#pragma unroll
    for (int ii = 0; ii < 8; ii++) {
        int r = (ii < 4) ? (tRow * 4 + ii) : (64 + tRow * 4 + ii - 4);
        int gr = m0 + r;
        if (gr >= NN) continue;
#pragma unroll
        for (int half = 0; half < 2; half++) {
            int c = half * 64 + tCol * 4;
            float4 o;
            o.x = fmaxf(fmaf(acc[ii][half * 4 + 0], Ssh[c + 0], Tsh[c + 0]), 0.f);
            o.y = fmaxf(fmaf(acc[ii][half * 4 + 1], Ssh[c + 1], Tsh[c + 1]), 0.f);
            o.z = fmaxf(fmaf(acc[ii][half * 4 + 2], Ssh[c + 2], Tsh[c + 2]), 0.f);
            o.w = fmaxf(fmaf(acc[ii][half * 4 + 3], Ssh[c + 3], Tsh[c + 3]), 0.f);
            *(float4*)(OUT + (size_t)gr * DD + c) = o;
        }
    }
}

// ---------------------------------------------------------------------------
// Final fused kernel:
// out = 0.5 * ( (h2 @ wp + bp) + relu(BN(xin2 @ w2 + b2)) )
// BM=64, 256 threads. Half the column-threads compute the wp path (A = h2),
// half compute the w2 GIN path (A = xin2).
// ---------------------------------------------------------------------------
__global__ __launch_bounds__(256) void final_kernel(
    const float* __restrict__ H2, const float* __restrict__ XIN2,
    const float* __restrict__ W2, const float* __restrict__ b2,
    const float* __restrict__ g2, const float* __restrict__ be2,
    const float* __restrict__ rm2, const float* __restrict__ rv2,
    const float* __restrict__ WP, const float* __restrict__ bp,
    float* __restrict__ OUT) {
    __shared__ float Ah[64][33];   // h2 tile [m][k]
    __shared__ float Ax[64][33];   // xin2 tile [m][k]
    __shared__ float Bws[32][41];  // WP tile [k][c]
    __shared__ float B2s[32][41];  // W2 tile [k][c]
    __shared__ float zsh[64][40];  // wp-path partial
    __shared__ float S2sh[40], T2sh[40], bpsh[40];

    const int tid = threadIdx.x;
    const int m0 = blockIdx.x * 64;

    if (tid < 40) {
        float s = g2[tid] * rsqrtf(rv2[tid] + 1e-5f);
        S2sh[tid] = s;
        T2sh[tid] = (b2[tid] - rm2[tid]) * s + be2[tid];
        bpsh[tid] = bp[tid];
    }

    float acc[4][5];
#pragma unroll
    for (int i = 0; i < 4; i++)
#pragma unroll
        for (int j = 0; j < 5; j++) acc[i][j] = 0.f;

    const int tRow = tid >> 4;            // 0..15 (x4 rows)
    const int tc = tid & 15;
    const bool pathW2 = (tc >= 8);
    const int cbase = (tc & 7) * 5;       // 8 groups x 5 cols = 40
    const int lr = tid >> 3;
    const int lc = (tid & 7) * 4;

    const float(*Apt)[33];
    const float(*Bpt)[41];

    for (int k0 = 0; k0 < 128; k0 += 32) {
        __syncthreads();
#pragma unroll
        for (int p = 0; p < 2; p++) {
            int row = p * 32 + lr;
            int gr = m0 + row;
            float4 hv = {0.f, 0.f, 0.f, 0.f};
            float4 xv = {0.f, 0.f, 0.f, 0.f};
            if (gr < NN) {
                hv = *(const float4*)(H2 + (size_t)gr * DD + k0 + lc);
                xv = *(const float4*)(XIN2 + (size_t)gr * DD + k0 + lc);
            }
            Ah[row][lc + 0] = hv.x; Ah[row][lc + 1] = hv.y;
            Ah[row][lc + 2] = hv.z; Ah[row][lc + 3] = hv.w;
            Ax[row][lc + 0] = xv.x; Ax[row][lc + 1] = xv.y;
            Ax[row][lc + 2] = xv.z; Ax[row][lc + 3] = xv.w;
        }
        for (int idx = tid; idx < 32 * 40; idx += 256) {
            int row = idx / 40;
            int c = idx - row * 40;
            Bws[row][c] = WP[(size_t)(k0 + row) * CC + c];
            B2s[row][c] = W2[(size_t)(k0 + row) * CC + c];
        }
        __syncthreads();

        Apt = pathW2 ? Ax : Ah;
        Bpt = pathW2 ? B2s : Bws;
#pragma unroll
        for (int k = 0; k < 32; k++) {
            float a[4];
#pragma unroll
            for (int i = 0; i < 4; i++) a[i] = Apt[tRow * 4 + i][k];
#pragma unroll
            for (int j = 0; j < 5; j++) {
                float bv = Bpt[k][cbase + j];
#pragma unroll
                for (int i = 0; i < 4; i++) acc[i][j] = fmaf(a[i], bv, acc[i][j]);
            }
        }
    }

    if (!pathW2) {
#pragma unroll
        for (int i = 0; i < 4; i++)
#pragma unroll
            for (int j = 0; j < 5; j++)
                zsh[tRow * 4 + i][cbase + j] = acc[i][j] + bpsh[cbase + j];
    }
    __syncthreads();
    if (pathW2) {
#pragma unroll
        for (int i = 0; i < 4; i++) {
            int gr = m0 + tRow * 4 + i;
            if (gr >= NN) continue;
#pragma unroll
            for (int j = 0; j < 5; j++) {
                int c = cbase + j;
                float h3 = fmaxf(fmaf(acc[i][j], S2sh[c], T2sh[c]), 0.f);
                OUT[(size_t)gr * CC + c] = 0.5f * (zsh[tRow * 4 + i][c] + h3);
            }
        }
    }
}

// ---------------------------------------------------------------------------
extern "C" void kernel_launch(void* const* d_in, const int* in_sizes, int n_in,
                              void* d_out, int out_size) {
    const float* h    = (const float*)d_in[0];
    const int*   esrc = (const int*)d_in[1];
    const int*   edst = (const int*)d_in[2];
    const float* mask = (const float*)d_in[3];
    const float* w0 = (const float*)d_in[4];
    const float* b0 = (const float*)d_in[5];
    const float* g0 = (const float*)d_in[6];
    const float* be0 = (const float*)d_in[7];
    const float* rm0 = (const float*)d_in[8];
    const float* rv0 = (const float*)d_in[9];
    const float* w1 = (const float*)d_in[10];
    const float* b1 = (const float*)d_in[11];
    const float* g1 = (const float*)d_in[12];
    const float* be1 = (const float*)d_in[13];
    const float* rm1 = (const float*)d_in[14];
    const float* rv1 = (const float*)d_in[15];
    const float* w2 = (const float*)d_in[16];
    const float* b2 = (const float*)d_in[17];
    const float* g2 = (const float*)d_in[18];
    const float* be2 = (const float*)d_in[19];
    const float* rm2 = (const float*)d_in[20];
    const float* rv2 = (const float*)d_in[21];
    const float* wp = (const float*)d_in[22];
    const float* bp = (const float*)d_in[23];
    float* out = (float*)d_out;

    float *xin, *h1b, *h2b, *xin2, *dinv, *cm;
    int *cnt, *cursor, *rowptr, *bsum, *csrc;
    cudaGetSymbolAddress((void**)&xin, g_xin);
    cudaGetSymbolAddress((void**)&h1b, g_h1);
    cudaGetSymbolAddress((void**)&h2b, g_h2);
    cudaGetSymbolAddress((void**)&xin2, g_xin2);
    cudaGetSymbolAddress((void**)&dinv, g_dinv);
    cudaGetSymbolAddress((void**)&cnt, g_cnt);
    cudaGetSymbolAddress((void**)&cursor, g_cursor);
    cudaGetSymbolAddress((void**)&rowptr, g_rowptr);
    cudaGetSymbolAddress((void**)&bsum, g_bsum);
    cudaGetSymbolAddress((void**)&csrc, g_csrc);
    cudaGetSymbolAddress((void**)&cm, g_cm);

    const int gemmBlocks = (NN + 127) / 128;
    const int aggBlocks = (NN * 32 + 255) / 256;

    // CSR build
    cudaMemsetAsync(cnt, 0, NN * sizeof(int));
    cudaMemsetAsync(cursor, 0, NN * sizeof(int));
    count_kernel<<<(EE + 255) / 256, 256>>>(edst, cnt);
    blocksum_kernel<<<NB, 1024>>>(cnt, bsum);
    scan_bsum_kernel<<<1, 32>>>(bsum);
    scan_write_kernel<<<NB, 1024>>>(cnt, bsum, rowptr);
    dinv_kernel<<<(NN + 255) / 256, 256>>>(cnt, dinv);
    scatter_kernel<<<(EE + 255) / 256, 256>>>(esrc, edst, mask, rowptr, cursor, csrc, cm);

    // Layer 0
    agg_xin_kernel<<<aggBlocks, 256>>>(h, rowptr, csrc, cm, dinv, xin);
    gin_gemm<<<gemmBlocks, 256>>>(xin, w0, b0, g0, be0, rm0, rv0, h1b);

    // Layer 1
    agg_xin_kernel<<<aggBlocks, 256>>>(h1b, rowptr, csrc, cm, dinv, xin);
    gin_gemm<<<gemmBlocks, 256>>>(xin, w1, b1, g1, be1, rm1, rv1, h2b);

    // Layer 2 aggregation + fused final
    agg_xin_kernel<<<aggBlocks, 256>>>(h2b, rowptr, csrc, cm, dinv, xin2);
    final_kernel<<<(NN + 63) / 64, 256>>>(h2b, xin2, w2, b2, g2, be2, rm2, rv2,
                                          wp, bp, out);
}

// round 6
// speedup vs baseline: 1.9881x; 1.5427x over previous
#include <cuda_runtime.h>
#include <cuda_bf16.h>
#include <cstdint>

#define NN 50000
#define DD 128
#define EE 800000
#define CC 40
#define NB 49   // ceil(NN/1024)

// ---------------------------------------------------------------------------
// PTX helpers (from verified sm_103a examples)
// ---------------------------------------------------------------------------
__device__ __forceinline__ uint32_t elect_one_pred() {
    uint32_t pred;
    asm volatile(
        "{\n\t.reg .pred p;\n\telect.sync _|p, 0xFFFFFFFF;\n\tselp.b32 %0, 1, 0, p;\n\t}"
        : "=r"(pred));
    return pred;
}

__device__ __forceinline__ uint32_t smem_to_u32(const void* smem_ptr) {
    uint32_t addr;
    asm("{ .reg .u64 tmp; cvta.to.shared.u64 tmp, %1; cvt.u32.u64 %0, tmp; }"
        : "=r"(addr) : "l"(smem_ptr));
    return addr;
}

#define MBARRIER_INIT(mbar, count) \
    asm volatile("mbarrier.init.shared.b64 [%0], %1;" \
                 :: "r"((uint32_t)(mbar)), "r"((uint32_t)(count)) : "memory")
#define MBARRIER_INVAL(mbar) \
    asm volatile("mbarrier.inval.shared.b64 [%0];" :: "r"((uint32_t)(mbar)) : "memory")

#define MBARRIER_WAIT_PARITY(mbar_smem_addr, phase_parity) do { \
    uint32_t _mbar = (uint32_t)(mbar_smem_addr); \
    uint32_t _parity = (uint32_t)(phase_parity); \
    uint32_t _done; \
    asm volatile( \
        "{\n\t.reg .pred p;\n\t" \
        "mbarrier.try_wait.parity.acquire.cta.shared::cta.b64 p, [%1], %2;\n\t" \
        "selp.b32 %0, 1, 0, p;\n\t}" \
        : "=r"(_done) : "r"(_mbar), "r"(_parity) : "memory"); \
    if (!_done) { \
        asm volatile( \
            "{\n\t.reg .pred P1;\n\t" \
            "WAIT_LOOP_%=:\n\t" \
            "mbarrier.try_wait.parity.acquire.cta.shared::cta.b64 P1, [%0], %1, 0x989680;\n\t" \
            "@P1 bra.uni WAIT_DONE_%=;\n\t" \
            "bra.uni WAIT_LOOP_%=;\n\t" \
            "WAIT_DONE_%=:\n\t}" \
            :: "r"(_mbar), "r"(_parity) : "memory"); \
    } \
} while(0)

// SW128 K-major descriptor base (LBO=1, SBO=64) == 0x4000404000010000
static constexpr uint64_t SMEM_DESC_BASE_SW128 =
    (uint64_t(2) << 61) | (uint64_t(1) << 46) | (uint64_t(64) << 32) | (uint64_t(1) << 16);
#define MAKE_SMEM_DESC(base_addr) \
    (SMEM_DESC_BASE_SW128 | ((uint64_t)((base_addr) >> 4) & 0x3FFF))
#define SW128(off) ((off) ^ (((off) >> 3) & 0x70))

// idesc: dtype=F32, atype=BF16, btype=BF16, N=128, M=128
// (formula reproduces test_mma's 0x8080490 for N=32, M=128)
#define MMA_IDESC ((1u << 4) | (1u << 7) | (1u << 10) | (16u << 17) | (8u << 24))

#if defined(__CUDA_ARCH_FEAT_SM103_ALL) || !defined(__CUDA_ARCH__)
#define HAS_TCGEN05 1
#else
#define HAS_TCGEN05 0
#endif

// ---------------------------------------------------------------------------
// Scratch (no allocations allowed -> device globals)
// ---------------------------------------------------------------------------
__device__ __align__(16) float g_h1[NN * DD];
__device__ __align__(16) float g_h2[NN * DD];
__device__ __align__(16) float g_xin2[NN * DD];
__device__ __align__(16) __nv_bfloat16 g_xh[NN * DD];
__device__ __align__(16) __nv_bfloat16 g_xl[NN * DD];
__device__ __align__(16) __nv_bfloat16 g_w0hi[DD * DD];
__device__ __align__(16) __nv_bfloat16 g_w0lo[DD * DD];
__device__ __align__(16) __nv_bfloat16 g_w1hi[DD * DD];
__device__ __align__(16) __nv_bfloat16 g_w1lo[DD * DD];
__device__ __align__(16) float g_dinv[NN];
__device__ __align__(16) int   g_cnt[NN];
__device__ __align__(16) int   g_cursor[NN];
__device__ __align__(16) int   g_rowptr[NN + 1];
__device__ __align__(16) int   g_bsum[64];
__device__ __align__(16) int   g_csrc[EE];
__device__ __align__(16) float g_cm[EE];

// ---------------------------------------------------------------------------
// CSR build
// ---------------------------------------------------------------------------
__global__ void count_kernel(const int* __restrict__ dst, int* __restrict__ cnt) {
    int i = blockIdx.x * blockDim.x + threadIdx.x;
    if (i < EE) atomicAdd(&cnt[dst[i]], 1);
}

__global__ void blocksum_kernel(const int* __restrict__ cnt, int* __restrict__ bsum) {
    __shared__ int sh[32];
    int tid = threadIdx.x;
    int i = blockIdx.x * 1024 + tid;
    int v = (i < NN) ? cnt[i] : 0;
    int lane = tid & 31, wid = tid >> 5;
#pragma unroll
    for (int o = 16; o > 0; o >>= 1) v += __shfl_down_sync(0xffffffffu, v, o);
    if (lane == 0) sh[wid] = v;
    __syncthreads();
    if (wid == 0) {
        int y = sh[lane];
#pragma unroll
        for (int o = 16; o > 0; o >>= 1) y += __shfl_down_sync(0xffffffffu, y, o);
        if (lane == 0) bsum[blockIdx.x] = y;
    }
}

__global__ void scan_bsum_kernel(int* __restrict__ bsum) {
    if (threadIdx.x == 0) {
        int acc = 0;
        for (int i = 0; i < NB; i++) { int t = bsum[i]; bsum[i] = acc; acc += t; }
    }
}

__global__ void scan_write_kernel(const int* __restrict__ cnt, const int* __restrict__ bsum,
                                  int* __restrict__ rowptr) {
    __shared__ int sh[32];
    int tid = threadIdx.x;
    int b = blockIdx.x;
    int i = b * 1024 + tid;
    int v = (i < NN) ? cnt[i] : 0;
    int lane = tid & 31, wid = tid >> 5;
    int x = v;
#pragma unroll
    for (int o = 1; o < 32; o <<= 1) {
        int t = __shfl_up_sync(0xffffffffu, x, o);
        if (lane >= o) x += t;
    }
    if (lane == 31) sh[wid] = x;
    __syncthreads();
    if (wid == 0) {
        int y = sh[lane];
#pragma unroll
        for (int o = 1; o < 32; o <<= 1) {
            int t = __shfl_up_sync(0xffffffffu, y, o);
            if (lane >= o) y += t;
        }
        sh[lane] = y;
    }
    __syncthreads();
    int incl = x + (wid ? sh[wid - 1] : 0) + bsum[b];
    if (i < NN) rowptr[i + 1] = incl;
    if (b == 0 && tid == 0) rowptr[0] = 0;
}

__global__ void dinv_kernel(const int* __restrict__ cnt, float* __restrict__ dinv) {
    int i = blockIdx.x * blockDim.x + threadIdx.x;
    if (i < NN) {
        int c = cnt[i];
        dinv[i] = c > 0 ? 1.0f / (float)c : 0.0f;
    }
}

__global__ void scatter_kernel(const int* __restrict__ esrc, const int* __restrict__ edst,
                               const float* __restrict__ mask, const int* __restrict__ rowptr,
                               int* __restrict__ cursor, int* __restrict__ csrc,
                               float* __restrict__ cm) {
    int e = blockIdx.x * blockDim.x + threadIdx.x;
    if (e >= EE) return;
    int d = edst[e];
    int pos = atomicAdd(&cursor[d], 1);
    int slot = rowptr[d] + pos;
    csrc[slot] = esrc[e];
    cm[slot] = mask[e];
}

// ---------------------------------------------------------------------------
// W pre-imaging: wT hi/lo in the exact SW128 smem image the MMA expects.
// ---------------------------------------------------------------------------
__global__ void wprep_kernel(const float* __restrict__ w,
                             __nv_bfloat16* __restrict__ hi,
                             __nv_bfloat16* __restrict__ lo) {
    int i = blockIdx.x * blockDim.x + threadIdx.x;
    if (i >= DD * DD) return;
    int k = i >> 7, n = i & 127;
    float v = w[i];
    __nv_bfloat16 h = __float2bfloat16(v);
    __nv_bfloat16 l = __float2bfloat16(v - __bfloat162float(h));
    uint32_t off = ((uint32_t)(k >> 6) << 14) | ((uint32_t)(n >> 3) << 10) |
                   ((uint32_t)(n & 7) << 7) | ((uint32_t)(k & 63) << 1);
    uint32_t sw = SW128(off);
    *(__nv_bfloat16*)((char*)hi + sw) = h;
    *(__nv_bfloat16*)((char*)lo + sw) = l;
}

// ---------------------------------------------------------------------------
// CSR aggregation -> xin split into bf16 hi/lo (for MMA layers)
// ---------------------------------------------------------------------------
__global__ __launch_bounds__(256) void agg_xin_bf16_kernel(
    const float* __restrict__ x, const int* __restrict__ rowptr,
    const int* __restrict__ csrc, const float* __restrict__ cm,
    const float* __restrict__ dinv,
    __nv_bfloat16* __restrict__ xh, __nv_bfloat16* __restrict__ xl) {
    int g = blockIdx.x * blockDim.x + threadIdx.x;
    int n = g >> 5;
    int lane = g & 31;
    if (n >= NN) return;
    int s = rowptr[n], e = rowptr[n + 1];
    float4 acc = {0.f, 0.f, 0.f, 0.f};
    int i = s;
    for (; i + 1 < e; i += 2) {
        int s0 = __ldg(&csrc[i]);
        int s1 = __ldg(&csrc[i + 1]);
        float m0 = __ldg(&cm[i]);
        float m1 = __ldg(&cm[i + 1]);
        float4 v0 = *(const float4*)(x + (size_t)s0 * DD + lane * 4);
        float4 v1 = *(const float4*)(x + (size_t)s1 * DD + lane * 4);
        acc.x = fmaf(v0.x, m0, acc.x); acc.y = fmaf(v0.y, m0, acc.y);
        acc.z = fmaf(v0.z, m0, acc.z); acc.w = fmaf(v0.w, m0, acc.w);
        acc.x = fmaf(v1.x, m1, acc.x); acc.y = fmaf(v1.y, m1, acc.y);
        acc.z = fmaf(v1.z, m1, acc.z); acc.w = fmaf(v1.w, m1, acc.w);
    }
    if (i < e) {
        int s0 = __ldg(&csrc[i]);
        float m0 = __ldg(&cm[i]);
        float4 v0 = *(const float4*)(x + (size_t)s0 * DD + lane * 4);
        acc.x = fmaf(v0.x, m0, acc.x); acc.y = fmaf(v0.y, m0, acc.y);
        acc.z = fmaf(v0.z, m0, acc.z); acc.w = fmaf(v0.w, m0, acc.w);
    }
    float di = dinv[n];
    float4 xv = *(const float4*)(x + (size_t)n * DD + lane * 4);
    float o[4];
    o[0] = fmaf(acc.x, di, xv.x);
    o[1] = fmaf(acc.y, di, xv.y);
    o[2] = fmaf(acc.z, di, xv.z);
    o[3] = fmaf(acc.w, di, xv.w);
    union { __nv_bfloat16 b[4]; uint2 u; } ph, pl;
#pragma unroll
    for (int j = 0; j < 4; j++) {
        __nv_bfloat16 h = __float2bfloat16(o[j]);
        ph.b[j] = h;
        pl.b[j] = __float2bfloat16(o[j] - __bfloat162float(h));
    }
    size_t base = (size_t)n * DD + lane * 4;
    *(uint2*)(xh + base) = ph.u;
    *(uint2*)(xl + base) = pl.u;
}

// ---------------------------------------------------------------------------
// CSR aggregation -> xin f32 (for the final SIMT kernel)
// ---------------------------------------------------------------------------
__global__ __launch_bounds__(256) void agg_xin_f32_kernel(
    const float* __restrict__ x, const int* __restrict__ rowptr,
    const int* __restrict__ csrc, const float* __restrict__ cm,
    const float* __restrict__ dinv, float* __restrict__ xin) {
    int g = blockIdx.x * blockDim.x + threadIdx.x;
    int n = g >> 5;
    int lane = g & 31;
    if (n >= NN) return;
    int s = rowptr[n], e = rowptr[n + 1];
    float4 acc = {0.f, 0.f, 0.f, 0.f};
    int i = s;
    for (; i + 1 < e; i += 2) {
        int s0 = __ldg(&csrc[i]);
        int s1 = __ldg(&csrc[i + 1]);
        float m0 = __ldg(&cm[i]);
        float m1 = __ldg(&cm[i + 1]);
        float4 v0 = *(const float4*)(x + (size_t)s0 * DD + lane * 4);
        float4 v1 = *(const float4*)(x + (size_t)s1 * DD + lane * 4);
        acc.x = fmaf(v0.x, m0, acc.x); acc.y = fmaf(v0.y, m0, acc.y);
        acc.z = fmaf(v0.z, m0, acc.z); acc.w = fmaf(v0.w, m0, acc.w);
        acc.x = fmaf(v1.x, m1, acc.x); acc.y = fmaf(v1.y, m1, acc.y);
        acc.z = fmaf(v1.z, m1, acc.z); acc.w = fmaf(v1.w, m1, acc.w);
    }
    if (i < e) {
        int s0 = __ldg(&csrc[i]);
        float m0 = __ldg(&cm[i]);
        float4 v0 = *(const float4*)(x + (size_t)s0 * DD + lane * 4);
        acc.x = fmaf(v0.x, m0, acc.x); acc.y = fmaf(v0.y, m0, acc.y);
        acc.z = fmaf(v0.z, m0, acc.z); acc.w = fmaf(v0.w, m0, acc.w);
    }
    float di = dinv[n];
    float4 xv = *(const float4*)(x + (size_t)n * DD + lane * 4);
    float4 o;
    o.x = fmaf(acc.x, di, xv.x);
    o.y = fmaf(acc.y, di, xv.y);
    o.z = fmaf(acc.z, di, xv.z);
    o.w = fmaf(acc.w, di, xv.w);
    *(float4*)(xin + (size_t)n * DD + lane * 4) = o;
}

// ---------------------------------------------------------------------------
// GEMM: OUT = relu(BN(XIN @ W)), bf16x3 split, M-tile 128, N=K=128.
// Structure mirrors test_mma_mxf8_512 / test_mma exactly (smem map, alloc,
// mbarrier, cluster annotation).
// ---------------------------------------------------------------------------
#define SM_PTR 0
#define SM_BAR 8
#define SMA_HI 1024
#define SMA_LO (SMA_HI + 32768)
#define SMB_HI (SMA_LO + 32768)
#define SMB_LO (SMB_HI + 32768)
#define SM_S   (SMB_LO + 32768)
#define SM_T   (SM_S + 512)
#define GEMM_SMEM (SM_T + 512)

__global__ __launch_bounds__(128) __cluster_dims__(1, 1, 1) void gin_gemm_mma(
    const __nv_bfloat16* __restrict__ XH, const __nv_bfloat16* __restrict__ XL,
    const __nv_bfloat16* __restrict__ BH, const __nv_bfloat16* __restrict__ BL,
    const float* __restrict__ bias, const float* __restrict__ gam,
    const float* __restrict__ bet, const float* __restrict__ rmean,
    const float* __restrict__ rvar, float* __restrict__ OUT) {
#if HAS_TCGEN05
    extern __shared__ char smem[];
    const uint32_t sb = smem_to_u32(smem);
    const int tid = threadIdx.x;
    const int wid = tid >> 5;
    const int lid = tid & 31;
    const int m0 = blockIdx.x * 128;
    float* Ssh = (float*)(smem + SM_S);
    float* Tsh = (float*)(smem + SM_T);

    // TMEM alloc (warp 0; others skip — matches test_mma/test_mma_mxf8_512)
    if (wid == 0) {
        asm volatile("tcgen05.alloc.cta_group::1.sync.aligned.shared::cta.b32 [%0], %1;"
                     :: "r"(sb + SM_PTR), "r"(512u) : "memory");
    }
    __syncthreads();
    uint32_t tmem_base;
    asm volatile("ld.shared.b32 %0, [%1];" : "=r"(tmem_base) : "r"(sb + SM_PTR));

    {
        float s = gam[tid] * rsqrtf(rvar[tid] + 1e-5f);
        Ssh[tid] = s;
        Tsh[tid] = (bias[tid] - rmean[tid]) * s + bet[tid];
    }

    // B: straight copy of pre-imaged blobs (already swizzled)
    {
        const uint4* bh = (const uint4*)BH;
        const uint4* bl = (const uint4*)BL;
        uint4* sh = (uint4*)(smem + SMB_HI);
        uint4* sl = (uint4*)(smem + SMB_LO);
#pragma unroll
        for (int q = 0; q < 16; q++) {
            int i = q * 128 + tid;
            sh[i] = bh[i];
            sl[i] = bl[i];
        }
    }
    // A: row-major gmem -> blocked swizzled smem, 16B chunks
    {
#pragma unroll
        for (int q = 0; q < 16; q++) {
            int cid = q * 128 + tid;       // 0..2047
            int r = cid >> 4;              // row in tile
            int k8 = (cid & 15) << 3;      // k start (8 bf16 = 16B)
            uint32_t off = ((uint32_t)(k8 >> 6) << 14) | ((uint32_t)(r >> 3) << 10) |
                           ((uint32_t)(r & 7) << 7) | ((uint32_t)(k8 & 63) << 1);
            uint32_t sw = SW128(off);
            int gr = m0 + r;
            uint4 vh = {0u, 0u, 0u, 0u}, vl = {0u, 0u, 0u, 0u};
            if (gr < NN) {
                size_t gaddr = (size_t)gr * DD + k8;
                vh = *(const uint4*)(XH + gaddr);
                vl = *(const uint4*)(XL + gaddr);
            }
            *(uint4*)(smem + SMA_HI + sw) = vh;
            *(uint4*)(smem + SMA_LO + sw) = vl;
        }
    }
    asm volatile("fence.proxy.async.shared::cta;" ::: "memory");
    __syncthreads();

    // MMA issue — exact test_mma sequence: elect-init, syncwarp, elect-issue.
    if (wid == 0) {
        if (elect_one_pred()) {
            MBARRIER_INIT(sb + SM_BAR, 1);
        }
        __syncwarp();

        uint64_t dah = MAKE_SMEM_DESC(sb + SMA_HI);
        uint64_t dal = MAKE_SMEM_DESC(sb + SMA_LO);
        uint64_t dbh = MAKE_SMEM_DESC(sb + SMB_HI);
        uint64_t dbl = MAKE_SMEM_DESC(sb + SMB_LO);

        if (elect_one_pred()) {
#pragma unroll
            for (int s = 0; s < 8; s++) {
                uint64_t off = (uint64_t)((s >> 2) * 1024 + (s & 3) * 2);
                uint32_t en0 = s > 0 ? 1u : 0u;
                asm volatile(
                    "{\n\t.reg .pred p;\n\tsetp.ne.u32 p, %5, 0;\n\t"
                    "tcgen05.mma.cta_group::1.kind::f16 [%0], %1, %2, %3, {%4, %4, %4, %4}, p;\n\t}"
                    :: "r"(tmem_base), "l"(dah + off), "l"(dbh + off), "r"(MMA_IDESC), "r"(0u), "r"(en0)
                    : "memory");
                asm volatile(
                    "{\n\t.reg .pred p;\n\tsetp.ne.u32 p, %5, 0;\n\t"
                    "tcgen05.mma.cta_group::1.kind::f16 [%0], %1, %2, %3, {%4, %4, %4, %4}, p;\n\t}"
                    :: "r"(tmem_base), "l"(dah + off), "l"(dbl + off), "r"(MMA_IDESC), "r"(0u), "r"(1u)
                    : "memory");
                asm volatile(
                    "{\n\t.reg .pred p;\n\tsetp.ne.u32 p, %5, 0;\n\t"
                    "tcgen05.mma.cta_group::1.kind::f16 [%0], %1, %2, %3, {%4, %4, %4, %4}, p;\n\t}"
                    :: "r"(tmem_base), "l"(dal + off), "l"(dbh + off), "r"(MMA_IDESC), "r"(0u), "r"(1u)
                    : "memory");
            }
            asm volatile(
                "tcgen05.commit.cta_group::1.mbarrier::arrive::one.shared::cluster.b64 [%0];"
                :: "r"(sb + SM_BAR) : "memory");
        }
    }

    // ALL warps wait for MMA completion, then read their subpartitions.
    __syncthreads();
    MBARRIER_WAIT_PARITY(sb + SM_BAR, 0);
    asm volatile("tcgen05.fence::after_thread_sync;" ::: "memory");

    int gr = m0 + wid * 32 + lid;
#pragma unroll
    for (int c0 = 0; c0 < 128; c0 += 32) {
        uint32_t dreg[32];
        asm volatile(
            "tcgen05.ld.sync.aligned.32x32b.x32.b32 "
            "{%0, %1, %2, %3, %4, %5, %6, %7, "
            " %8, %9, %10, %11, %12, %13, %14, %15, "
            " %16, %17, %18, %19, %20, %21, %22, %23, "
            " %24, %25, %26, %27, %28, %29, %30, %31}, [%32];"
            : "=r"(dreg[0]),  "=r"(dreg[1]),  "=r"(dreg[2]),  "=r"(dreg[3]),
              "=r"(dreg[4]),  "=r"(dreg[5]),  "=r"(dreg[6]),  "=r"(dreg[7]),
              "=r"(dreg[8]),  "=r"(dreg[9]),  "=r"(dreg[10]), "=r"(dreg[11]),
              "=r"(dreg[12]), "=r"(dreg[13]), "=r"(dreg[14]), "=r"(dreg[15]),
              "=r"(dreg[16]), "=r"(dreg[17]), "=r"(dreg[18]), "=r"(dreg[19]),
              "=r"(dreg[20]), "=r"(dreg[21]), "=r"(dreg[22]), "=r"(dreg[23]),
              "=r"(dreg[24]), "=r"(dreg[25]), "=r"(dreg[26]), "=r"(dreg[27]),
              "=r"(dreg[28]), "=r"(dreg[29]), "=r"(dreg[30]), "=r"(dreg[31])
            : "r"(tmem_base + c0));
        asm volatile("tcgen05.wait::ld.sync.aligned;" ::: "memory");
        if (gr < NN) {
#pragma unroll
            for (int j4 = 0; j4 < 8; j4++) {
                int c = c0 + j4 * 4;
                float4 o;
                o.x = fmaxf(fmaf(__uint_as_float(dreg[j4 * 4 + 0]), Ssh[c + 0], Tsh[c + 0]), 0.f);
                o.y = fmaxf(fmaf(__uint_as_float(dreg[j4 * 4 + 1]), Ssh[c + 1], Tsh[c + 1]), 0.f);
                o.z = fmaxf(fmaf(__uint_as_float(dreg[j4 * 4 + 2]), Ssh[c + 2], Tsh[c + 2]), 0.f);
                o.w = fmaxf(fmaf(__uint_as_float(dreg[j4 * 4 + 3]), Ssh[c + 3], Tsh[c + 3]), 0.f);
                *(float4*)(OUT + (size_t)gr * DD + c) = o;
            }
        }
    }
    asm volatile("tcgen05.fence::before_thread_sync;" ::: "memory");
    __syncthreads();
    if (wid == 0) {
        if (elect_one_pred()) {
            MBARRIER_INVAL(sb + SM_BAR);
        }
        asm volatile("tcgen05.dealloc.cta_group::1.sync.aligned.b32 %0, %1;"
                     :: "r"(tmem_base), "r"(512u));
    }
#else
    // SIMT fallback (baseline compute_103 pass only).
    extern __shared__ char smem[];
    float* Ssh = (float*)(smem + SM_S);
    float* Tsh = (float*)(smem + SM_T);
    const int tid = threadIdx.x;
    const int m0 = blockIdx.x * 128;
    {
        float s = gam[tid] * rsqrtf(rvar[tid] + 1e-5f);
        Ssh[tid] = s;
        Tsh[tid] = (bias[tid] - rmean[tid]) * s + bet[tid];
    }
    __syncthreads();
    int gr = m0 + tid;
    if (gr < NN) {
        float a[DD];
#pragma unroll 8
        for (int k = 0; k < DD; k++)
            a[k] = __bfloat162float(XH[(size_t)gr * DD + k]) +
                   __bfloat162float(XL[(size_t)gr * DD + k]);
        for (int n = 0; n < DD; n++) {
            float acc = 0.f;
#pragma unroll 8
            for (int k = 0; k < DD; k++) {
                uint32_t off = ((uint32_t)(k >> 6) << 14) | ((uint32_t)(n >> 3) << 10) |
                               ((uint32_t)(n & 7) << 7) | ((uint32_t)(k & 63) << 1);
                uint32_t sw = SW128(off);
                float wv = __bfloat162float(*(const __nv_bfloat16*)((const char*)BH + sw)) +
                           __bfloat162float(*(const __nv_bfloat16*)((const char*)BL + sw));
                acc = fmaf(a[k], wv, acc);
            }
            OUT[(size_t)gr * DD + n] = fmaxf(fmaf(acc, Ssh[n], Tsh[n]), 0.f);
        }
    }
#endif
}

// ---------------------------------------------------------------------------
// Final fused kernel (SIMT f32):
// out = 0.5 * ( (h2 @ wp + bp) + relu(BN(xin2 @ w2 + b2)) )
// ---------------------------------------------------------------------------
__global__ __launch_bounds__(256) void final_kernel(
    const float* __restrict__ H2, const float* __restrict__ XIN2,
    const float* __restrict__ W2, const float* __restrict__ b2,
    const float* __restrict__ g2, const float* __restrict__ be2,
    const float* __restrict__ rm2, const float* __restrict__ rv2,
    const float* __restrict__ WP, const float* __restrict__ bp,
    float* __restrict__ OUT) {
    __shared__ float Ah[64][33];
    __shared__ float Ax[64][33];
    __shared__ float Bws[32][41];
    __shared__ float B2s[32][41];
    __shared__ float zsh[64][40];
    __shared__ float S2sh[40], T2sh[40], bpsh[40];

    const int tid = threadIdx.x;
    const int m0 = blockIdx.x * 64;

    if (tid < 40) {
        float s = g2[tid] * rsqrtf(rv2[tid] + 1e-5f);
        S2sh[tid] = s;
        T2sh[tid] = (b2[tid] - rm2[tid]) * s + be2[tid];
        bpsh[tid] = bp[tid];
    }

    float acc[4][5];
#pragma unroll
    for (int i = 0; i < 4; i++)
#pragma unroll
        for (int j = 0; j < 5; j++) acc[i][j] = 0.f;

    const int tRow = tid >> 4;
    const int tc = tid & 15;
    const bool pathW2 = (tc >= 8);
    const int cbase = (tc & 7) * 5;
    const int lr = tid >> 3;
    const int lc = (tid & 7) * 4;

    const float(*Apt)[33];
    const float(*Bpt)[41];

    for (int k0 = 0; k0 < 128; k0 += 32) {
        __syncthreads();
#pragma unroll
        for (int p = 0; p < 2; p++) {
            int row = p * 32 + lr;
            int gr = m0 + row;
            float4 hv = {0.f, 0.f, 0.f, 0.f};
            float4 xv = {0.f, 0.f, 0.f, 0.f};
            if (gr < NN) {
                hv = *(const float4*)(H2 + (size_t)gr * DD + k0 + lc);
                xv = *(const float4*)(XIN2 + (size_t)gr * DD + k0 + lc);
            }
            Ah[row][lc + 0] = hv.x; Ah[row][lc + 1] = hv.y;
            Ah[row][lc + 2] = hv.z; Ah[row][lc + 3] = hv.w;
            Ax[row][lc + 0] = xv.x; Ax[row][lc + 1] = xv.y;
            Ax[row][lc + 2] = xv.z; Ax[row][lc + 3] = xv.w;
        }
        for (int idx = tid; idx < 32 * 40; idx += 256) {
            int row = idx / 40;
            int c = idx - row * 40;
            Bws[row][c] = WP[(size_t)(k0 + row) * CC + c];
            B2s[row][c] = W2[(size_t)(k0 + row) * CC + c];
        }
        __syncthreads();

        Apt = pathW2 ? Ax : Ah;
        Bpt = pathW2 ? B2s : Bws;
#pragma unroll
        for (int k = 0; k < 32; k++) {
            float a[4];
#pragma unroll
            for (int i = 0; i < 4; i++) a[i] = Apt[tRow * 4 + i][k];
#pragma unroll
            for (int j = 0; j < 5; j++) {
                float bv = Bpt[k][cbase + j];
#pragma unroll
                for (int i = 0; i < 4; i++) acc[i][j] = fmaf(a[i], bv, acc[i][j]);
            }
        }
    }

    if (!pathW2) {
#pragma unroll
        for (int i = 0; i < 4; i++)
#pragma unroll
            for (int j = 0; j < 5; j++)
                zsh[tRow * 4 + i][cbase + j] = acc[i][j] + bpsh[cbase + j];
    }
    __syncthreads();
    if (pathW2) {
#pragma unroll
        for (int i = 0; i < 4; i++) {
            int gr = m0 + tRow * 4 + i;
            if (gr >= NN) continue;
#pragma unroll
            for (int j = 0; j < 5; j++) {
                int c = cbase + j;
                float h3 = fmaxf(fmaf(acc[i][j], S2sh[c], T2sh[c]), 0.f);
                OUT[(size_t)gr * CC + c] = 0.5f * (zsh[tRow * 4 + i][c] + h3);
            }
        }
    }
}

// ---------------------------------------------------------------------------
extern "C" void kernel_launch(void* const* d_in, const int* in_sizes, int n_in,
                              void* d_out, int out_size) {
    const float* h    = (const float*)d_in[0];
    const int*   esrc = (const int*)d_in[1];
    const int*   edst = (const int*)d_in[2];
    const float* mask = (const float*)d_in[3];
    const float* w0 = (const float*)d_in[4];
    const float* b0 = (const float*)d_in[5];
    const float* g0 = (const float*)d_in[6];
    const float* be0 = (const float*)d_in[7];
    const float* rm0 = (const float*)d_in[8];
    const float* rv0 = (const float*)d_in[9];
    const float* w1 = (const float*)d_in[10];
    const float* b1 = (const float*)d_in[11];
    const float* g1 = (const float*)d_in[12];
    const float* be1 = (const float*)d_in[13];
    const float* rm1 = (const float*)d_in[14];
    const float* rv1 = (const float*)d_in[15];
    const float* w2 = (const float*)d_in[16];
    const float* b2 = (const float*)d_in[17];
    const float* g2 = (const float*)d_in[18];
    const float* be2 = (const float*)d_in[19];
    const float* rm2 = (const float*)d_in[20];
    const float* rv2 = (const float*)d_in[21];
    const float* wp = (const float*)d_in[22];
    const float* bp = (const float*)d_in[23];
    float* out = (float*)d_out;

    float *h1b, *h2b, *xin2, *dinv, *cm;
    __nv_bfloat16 *xh, *xl, *w0hi, *w0lo, *w1hi, *w1lo;
    int *cnt, *cursor, *rowptr, *bsum, *csrc;
    cudaGetSymbolAddress((void**)&h1b, g_h1);
    cudaGetSymbolAddress((void**)&h2b, g_h2);
    cudaGetSymbolAddress((void**)&xin2, g_xin2);
    cudaGetSymbolAddress((void**)&xh, g_xh);
    cudaGetSymbolAddress((void**)&xl, g_xl);
    cudaGetSymbolAddress((void**)&w0hi, g_w0hi);
    cudaGetSymbolAddress((void**)&w0lo, g_w0lo);
    cudaGetSymbolAddress((void**)&w1hi, g_w1hi);
    cudaGetSymbolAddress((void**)&w1lo, g_w1lo);
    cudaGetSymbolAddress((void**)&dinv, g_dinv);
    cudaGetSymbolAddress((void**)&cnt, g_cnt);
    cudaGetSymbolAddress((void**)&cursor, g_cursor);
    cudaGetSymbolAddress((void**)&rowptr, g_rowptr);
    cudaGetSymbolAddress((void**)&bsum, g_bsum);
    cudaGetSymbolAddress((void**)&csrc, g_csrc);
    cudaGetSymbolAddress((void**)&cm, g_cm);

    cudaFuncSetAttribute(gin_gemm_mma, cudaFuncAttributeMaxDynamicSharedMemorySize,
                         GEMM_SMEM);

    const int mmaBlocks = (NN + 127) / 128;   // 391
    const int aggBlocks = (NN * 32 + 255) / 256;

    // CSR build + W pre-imaging
    cudaMemsetAsync(cnt, 0, NN * sizeof(int));
    cudaMemsetAsync(cursor, 0, NN * sizeof(int));
    count_kernel<<<(EE + 255) / 256, 256>>>(edst, cnt);
    wprep_kernel<<<(DD * DD + 255) / 256, 256>>>(w0, w0hi, w0lo);
    wprep_kernel<<<(DD * DD + 255) / 256, 256>>>(w1, w1hi, w1lo);
    blocksum_kernel<<<NB, 1024>>>(cnt, bsum);
    scan_bsum_kernel<<<1, 32>>>(bsum);
    scan_write_kernel<<<NB, 1024>>>(cnt, bsum, rowptr);
    dinv_kernel<<<(NN + 255) / 256, 256>>>(cnt, dinv);
    scatter_kernel<<<(EE + 255) / 256, 256>>>(esrc, edst, mask, rowptr, cursor, csrc, cm);

    // Layer 0
    agg_xin_bf16_kernel<<<aggBlocks, 256>>>(h, rowptr, csrc, cm, dinv, xh, xl);
    gin_gemm_mma<<<mmaBlocks, 128, GEMM_SMEM>>>(xh, xl, w0hi, w0lo,
                                                b0, g0, be0, rm0, rv0, h1b);

    // Layer 1
    agg_xin_bf16_kernel<<<aggBlocks, 256>>>(h1b, rowptr, csrc, cm, dinv, xh, xl);
    gin_gemm_mma<<<mmaBlocks, 128, GEMM_SMEM>>>(xh, xl, w1hi, w1lo,
                                                b1, g1, be1, rm1, rv1, h2b);

    // Layer 2 aggregation + fused final
    agg_xin_f32_kernel<<<aggBlocks, 256>>>(h2b, rowptr, csrc, cm, dinv, xin2);
    final_kernel<<<(NN + 63) / 64, 256>>>(h2b, xin2, w2, b2, g2, be2, rm2, rv2,
                                          wp, bp, out);
}

// round 7
// speedup vs baseline: 2.5309x; 1.2730x over previous
#include <cuda_runtime.h>
#include <cuda_bf16.h>
#include <cstdint>

#define NN 50000
#define DD 128
#define EE 800000
#define CC 40
#define NB 49   // ceil(NN/1024)

// ---------------------------------------------------------------------------
// PTX helpers (from verified sm_103a examples)
// ---------------------------------------------------------------------------
__device__ __forceinline__ uint32_t elect_one_pred() {
    uint32_t pred;
    asm volatile(
        "{\n\t.reg .pred p;\n\telect.sync _|p, 0xFFFFFFFF;\n\tselp.b32 %0, 1, 0, p;\n\t}"
        : "=r"(pred));
    return pred;
}

__device__ __forceinline__ uint32_t smem_to_u32(const void* smem_ptr) {
    uint32_t addr;
    asm("{ .reg .u64 tmp; cvta.to.shared.u64 tmp, %1; cvt.u32.u64 %0, tmp; }"
        : "=r"(addr) : "l"(smem_ptr));
    return addr;
}

#define MBARRIER_INIT(mbar, count) \
    asm volatile("mbarrier.init.shared.b64 [%0], %1;" \
                 :: "r"((uint32_t)(mbar)), "r"((uint32_t)(count)) : "memory")
#define MBARRIER_INVAL(mbar) \
    asm volatile("mbarrier.inval.shared.b64 [%0];" :: "r"((uint32_t)(mbar)) : "memory")

#define MBARRIER_WAIT_PARITY(mbar_smem_addr, phase_parity) do { \
    uint32_t _mbar = (uint32_t)(mbar_smem_addr); \
    uint32_t _parity = (uint32_t)(phase_parity); \
    uint32_t _done; \
    asm volatile( \
        "{\n\t.reg .pred p;\n\t" \
        "mbarrier.try_wait.parity.acquire.cta.shared::cta.b64 p, [%1], %2;\n\t" \
        "selp.b32 %0, 1, 0, p;\n\t}" \
        : "=r"(_done) : "r"(_mbar), "r"(_parity) : "memory"); \
    if (!_done) { \
        asm volatile( \
            "{\n\t.reg .pred P1;\n\t" \
            "WAIT_LOOP_%=:\n\t" \
            "mbarrier.try_wait.parity.acquire.cta.shared::cta.b64 P1, [%0], %1, 0x989680;\n\t" \
            "@P1 bra.uni WAIT_DONE_%=;\n\t" \
            "bra.uni WAIT_LOOP_%=;\n\t" \
            "WAIT_DONE_%=:\n\t}" \
            :: "r"(_mbar), "r"(_parity) : "memory"); \
    } \
} while(0)

#define TC_MMA_F16(dt, ad, bd, idesc, en) \
    asm volatile( \
        "{\n\t.reg .pred p;\n\tsetp.ne.u32 p, %5, 0;\n\t" \
        "tcgen05.mma.cta_group::1.kind::f16 [%0], %1, %2, %3, {%4, %4, %4, %4}, p;\n\t}" \
        :: "r"(dt), "l"(ad), "l"(bd), "r"(idesc), "r"(0u), "r"((uint32_t)(en)) \
        : "memory")

#define TC_LD_X32(r, addr) \
    asm volatile( \
        "tcgen05.ld.sync.aligned.32x32b.x32.b32 " \
        "{%0, %1, %2, %3, %4, %5, %6, %7, " \
        " %8, %9, %10, %11, %12, %13, %14, %15, " \
        " %16, %17, %18, %19, %20, %21, %22, %23, " \
        " %24, %25, %26, %27, %28, %29, %30, %31}, [%32];" \
        : "=r"((r)[0]),  "=r"((r)[1]),  "=r"((r)[2]),  "=r"((r)[3]), \
          "=r"((r)[4]),  "=r"((r)[5]),  "=r"((r)[6]),  "=r"((r)[7]), \
          "=r"((r)[8]),  "=r"((r)[9]),  "=r"((r)[10]), "=r"((r)[11]), \
          "=r"((r)[12]), "=r"((r)[13]), "=r"((r)[14]), "=r"((r)[15]), \
          "=r"((r)[16]), "=r"((r)[17]), "=r"((r)[18]), "=r"((r)[19]), \
          "=r"((r)[20]), "=r"((r)[21]), "=r"((r)[22]), "=r"((r)[23]), \
          "=r"((r)[24]), "=r"((r)[25]), "=r"((r)[26]), "=r"((r)[27]), \
          "=r"((r)[28]), "=r"((r)[29]), "=r"((r)[30]), "=r"((r)[31]) \
        : "r"(addr))

#define TC_LD_X8(r, addr) \
    asm volatile( \
        "tcgen05.ld.sync.aligned.32x32b.x8.b32 " \
        "{%0, %1, %2, %3, %4, %5, %6, %7}, [%8];" \
        : "=r"((r)[0]), "=r"((r)[1]), "=r"((r)[2]), "=r"((r)[3]), \
          "=r"((r)[4]), "=r"((r)[5]), "=r"((r)[6]), "=r"((r)[7]) \
        : "r"(addr))

#define TC_WAIT_LD() asm volatile("tcgen05.wait::ld.sync.aligned;" ::: "memory")

// SW128 K-major descriptor base (LBO=1, SBO=64) == 0x4000404000010000
static constexpr uint64_t SMEM_DESC_BASE_SW128 =
    (uint64_t(2) << 61) | (uint64_t(1) << 46) | (uint64_t(64) << 32) | (uint64_t(1) << 16);
#define MAKE_SMEM_DESC(base_addr) \
    (SMEM_DESC_BASE_SW128 | ((uint64_t)((base_addr) >> 4) & 0x3FFF))
#define SW128(off) ((off) ^ (((off) >> 3) & 0x70))

// idesc: dtype=F32, atype=BF16, btype=BF16, M=128
#define MMA_IDESC128 ((1u << 4) | (1u << 7) | (1u << 10) | (16u << 17) | (8u << 24))
#define MMA_IDESC40  ((1u << 4) | (1u << 7) | (1u << 10) | (5u << 17)  | (8u << 24))

#if defined(__CUDA_ARCH_FEAT_SM103_ALL) || !defined(__CUDA_ARCH__)
#define HAS_TCGEN05 1
#else
#define HAS_TCGEN05 0
#endif

// ---------------------------------------------------------------------------
// Scratch (device globals; no allocations allowed)
// ---------------------------------------------------------------------------
__device__ __align__(16) float g_h1[NN * DD];
__device__ __align__(16) float g_h2[NN * DD];
__device__ __align__(16) __nv_bfloat16 g_xh[NN * DD];
__device__ __align__(16) __nv_bfloat16 g_xl[NN * DD];
__device__ __align__(16) __nv_bfloat16 g_w0hi[DD * DD];
__device__ __align__(16) __nv_bfloat16 g_w0lo[DD * DD];
__device__ __align__(16) __nv_bfloat16 g_w1hi[DD * DD];
__device__ __align__(16) __nv_bfloat16 g_w1lo[DD * DD];
__device__ __align__(16) __nv_bfloat16 g_w2hi[2 * 5 * 512];   // 5120 elems (10240B)
__device__ __align__(16) __nv_bfloat16 g_w2lo[2 * 5 * 512];
__device__ __align__(16) __nv_bfloat16 g_wphi[2 * 5 * 512];
__device__ __align__(16) __nv_bfloat16 g_wplo[2 * 5 * 512];
__device__ __align__(16) float g_dinv[NN];
__device__ __align__(16) int   g_cnt[NN];
__device__ __align__(16) int   g_cursor[NN];
__device__ __align__(16) int   g_rowptr[NN + 1];
__device__ __align__(16) int   g_bsum[64];
__device__ __align__(16) int   g_csrc[EE];
__device__ __align__(16) float g_cm[EE];

// ---------------------------------------------------------------------------
// Fused prep: blocks [0,3125) count degrees; remaining blocks pre-image the
// four weight matrices as SW128-swizzled bf16 hi/lo blobs.
//  128-col image: off(n,k) = (k>>6)*16384 + (n>>3)*1024 + (n&7)*128 + (k&63)*2
//   40-col image: off(n,k) = (k>>6)*5120  + (n>>3)*1024 + (n&7)*128 + (k&63)*2
// ---------------------------------------------------------------------------
#define CNT_BLKS 3125      // EE/256
#define W128_BLKS 64       // 16384/256
#define W40_BLKS 20        // 5120/256
#define PREP_BLKS (CNT_BLKS + 2 * W128_BLKS + 2 * W40_BLKS)

__device__ __forceinline__ void wimg128(const float* w, __nv_bfloat16* hi,
                                        __nv_bfloat16* lo, int i) {
    int k = i >> 7, n = i & 127;
    float v = w[i];
    __nv_bfloat16 h = __float2bfloat16(v);
    __nv_bfloat16 l = __float2bfloat16(v - __bfloat162float(h));
    uint32_t off = ((uint32_t)(k >> 6) << 14) | ((uint32_t)(n >> 3) << 10) |
                   ((uint32_t)(n & 7) << 7) | ((uint32_t)(k & 63) << 1);
    uint32_t sw = SW128(off);
    *(__nv_bfloat16*)((char*)hi + sw) = h;
    *(__nv_bfloat16*)((char*)lo + sw) = l;
}

__device__ __forceinline__ void wimg40(const float* w, __nv_bfloat16* hi,
                                       __nv_bfloat16* lo, int i) {
    int k = i / CC, n = i - k * CC;
    float v = w[i];
    __nv_bfloat16 h = __float2bfloat16(v);
    __nv_bfloat16 l = __float2bfloat16(v - __bfloat162float(h));
    uint32_t off = (uint32_t)(k >> 6) * 5120u + ((uint32_t)(n >> 3) << 10) |
                   ((uint32_t)(n & 7) << 7) | ((uint32_t)(k & 63) << 1);
    uint32_t sw = SW128(off);
    *(__nv_bfloat16*)((char*)hi + sw) = h;
    *(__nv_bfloat16*)((char*)lo + sw) = l;
}

__global__ void prep_kernel(const int* __restrict__ edst, int* __restrict__ cnt,
                            const float* __restrict__ w0, __nv_bfloat16* w0h, __nv_bfloat16* w0l,
                            const float* __restrict__ w1, __nv_bfloat16* w1h, __nv_bfloat16* w1l,
                            const float* __restrict__ w2, __nv_bfloat16* w2h, __nv_bfloat16* w2l,
                            const float* __restrict__ wp, __nv_bfloat16* wph, __nv_bfloat16* wpl) {
    int b = blockIdx.x;
    int t = threadIdx.x;
    if (b < CNT_BLKS) {
        int e = b * 256 + t;
        if (e < EE) atomicAdd(&cnt[edst[e]], 1);
    } else if (b < CNT_BLKS + W128_BLKS) {
        wimg128(w0, w0h, w0l, (b - CNT_BLKS) * 256 + t);
    } else if (b < CNT_BLKS + 2 * W128_BLKS) {
        wimg128(w1, w1h, w1l, (b - CNT_BLKS - W128_BLKS) * 256 + t);
    } else if (b < CNT_BLKS + 2 * W128_BLKS + W40_BLKS) {
        wimg40(w2, w2h, w2l, (b - CNT_BLKS - 2 * W128_BLKS) * 256 + t);
    } else {
        wimg40(wp, wph, wpl, (b - CNT_BLKS - 2 * W128_BLKS - W40_BLKS) * 256 + t);
    }
}

// ---------------------------------------------------------------------------
// Two-level exclusive scan of cnt -> rowptr; also writes cursor (=row start)
// and dinv.
// ---------------------------------------------------------------------------
__global__ void blocksum_kernel(const int* __restrict__ cnt, int* __restrict__ bsum) {
    __shared__ int sh[32];
    int tid = threadIdx.x;
    int i = blockIdx.x * 1024 + tid;
    int v = (i < NN) ? cnt[i] : 0;
    int lane = tid & 31, wid = tid >> 5;
#pragma unroll
    for (int o = 16; o > 0; o >>= 1) v += __shfl_down_sync(0xffffffffu, v, o);
    if (lane == 0) sh[wid] = v;
    __syncthreads();
    if (wid == 0) {
        int y = sh[lane];
#pragma unroll
        for (int o = 16; o > 0; o >>= 1) y += __shfl_down_sync(0xffffffffu, y, o);
        if (lane == 0) bsum[blockIdx.x] = y;
    }
}

__global__ void scan_bsum_kernel(int* __restrict__ bsum) {
    if (threadIdx.x == 0) {
        int acc = 0;
        for (int i = 0; i < NB; i++) { int t = bsum[i]; bsum[i] = acc; acc += t; }
    }
}

__global__ void scan_write_kernel(const int* __restrict__ cnt, const int* __restrict__ bsum,
                                  int* __restrict__ rowptr, int* __restrict__ cursor,
                                  float* __restrict__ dinv) {
    __shared__ int sh[32];
    int tid = threadIdx.x;
    int b = blockIdx.x;
    int i = b * 1024 + tid;
    int v = (i < NN) ? cnt[i] : 0;
    int lane = tid & 31, wid = tid >> 5;
    int x = v;
#pragma unroll
    for (int o = 1; o < 32; o <<= 1) {
        int t = __shfl_up_sync(0xffffffffu, x, o);
        if (lane >= o) x += t;
    }
    if (lane == 31) sh[wid] = x;
    __syncthreads();
    if (wid == 0) {
        int y = sh[lane];
#pragma unroll
        for (int o = 1; o < 32; o <<= 1) {
            int t = __shfl_up_sync(0xffffffffu, y, o);
            if (lane >= o) y += t;
        }
        sh[lane] = y;
    }
    __syncthreads();
    int incl = x + (wid ? sh[wid - 1] : 0) + bsum[b];
    if (i < NN) {
        rowptr[i + 1] = incl;
        cursor[i] = incl - v;   // exclusive start
        dinv[i] = v > 0 ? 1.0f / (float)v : 0.0f;
    }
    if (b == 0 && tid == 0) rowptr[0] = 0;
}

__global__ void scatter_kernel(const int* __restrict__ esrc, const int* __restrict__ edst,
                               const float* __restrict__ mask,
                               int* __restrict__ cursor, int* __restrict__ csrc,
                               float* __restrict__ cm) {
    int e = blockIdx.x * blockDim.x + threadIdx.x;
    if (e >= EE) return;
    int slot = atomicAdd(&cursor[edst[e]], 1);
    csrc[slot] = esrc[e];
    cm[slot] = mask[e];
}

// ---------------------------------------------------------------------------
// CSR aggregation: warp per node. xin = x + dinv*sum(mask*x[src]); bf16 hi/lo.
// ---------------------------------------------------------------------------
__global__ __launch_bounds__(256) void agg_xin_bf16_kernel(
    const float* __restrict__ x, const int* __restrict__ rowptr,
    const int* __restrict__ csrc, const float* __restrict__ cm,
    const float* __restrict__ dinv,
    __nv_bfloat16* __restrict__ xh, __nv_bfloat16* __restrict__ xl) {
    int g = blockIdx.x * blockDim.x + threadIdx.x;
    int n = g >> 5;
    int lane = g & 31;
    if (n >= NN) return;
    int s = rowptr[n], e = rowptr[n + 1];
    float4 acc = {0.f, 0.f, 0.f, 0.f};
    int i = s;
    for (; i + 1 < e; i += 2) {
        int s0 = __ldg(&csrc[i]);
        int s1 = __ldg(&csrc[i + 1]);
        float m0 = __ldg(&cm[i]);
        float m1 = __ldg(&cm[i + 1]);
        float4 v0 = *(const float4*)(x + (size_t)s0 * DD + lane * 4);
        float4 v1 = *(const float4*)(x + (size_t)s1 * DD + lane * 4);
        acc.x = fmaf(v0.x, m0, acc.x); acc.y = fmaf(v0.y, m0, acc.y);
        acc.z = fmaf(v0.z, m0, acc.z); acc.w = fmaf(v0.w, m0, acc.w);
        acc.x = fmaf(v1.x, m1, acc.x); acc.y = fmaf(v1.y, m1, acc.y);
        acc.z = fmaf(v1.z, m1, acc.z); acc.w = fmaf(v1.w, m1, acc.w);
    }
    if (i < e) {
        int s0 = __ldg(&csrc[i]);
        float m0 = __ldg(&cm[i]);
        float4 v0 = *(const float4*)(x + (size_t)s0 * DD + lane * 4);
        acc.x = fmaf(v0.x, m0, acc.x); acc.y = fmaf(v0.y, m0, acc.y);
        acc.z = fmaf(v0.z, m0, acc.z); acc.w = fmaf(v0.w, m0, acc.w);
    }
    float di = dinv[n];
    float4 xv = *(const float4*)(x + (size_t)n * DD + lane * 4);
    float o[4];
    o[0] = fmaf(acc.x, di, xv.x);
    o[1] = fmaf(acc.y, di, xv.y);
    o[2] = fmaf(acc.z, di, xv.z);
    o[3] = fmaf(acc.w, di, xv.w);
    union { __nv_bfloat16 b[4]; uint2 u; } ph, pl;
#pragma unroll
    for (int j = 0; j < 4; j++) {
        __nv_bfloat16 h = __float2bfloat16(o[j]);
        ph.b[j] = h;
        pl.b[j] = __float2bfloat16(o[j] - __bfloat162float(h));
    }
    size_t base = (size_t)n * DD + lane * 4;
    *(uint2*)(xh + base) = ph.u;
    *(uint2*)(xl + base) = pl.u;
}

// ---------------------------------------------------------------------------
// GIN layer GEMM (tcgen05): OUT = relu(BN(XIN @ W)), bf16x3, M-tile 128.
// ---------------------------------------------------------------------------
#define SM_PTR 0
#define SM_BAR 8
#define SMA_HI 1024
#define SMA_LO (SMA_HI + 32768)
#define SMB_HI (SMA_LO + 32768)
#define SMB_LO (SMB_HI + 32768)
#define SM_S   (SMB_LO + 32768)
#define SM_T   (SM_S + 512)
#define GEMM_SMEM (SM_T + 512)

__global__ __launch_bounds__(256) __cluster_dims__(1, 1, 1) void gin_gemm_mma(
    const __nv_bfloat16* __restrict__ XH, const __nv_bfloat16* __restrict__ XL,
    const __nv_bfloat16* __restrict__ BH, const __nv_bfloat16* __restrict__ BL,
    const float* __restrict__ bias, const float* __restrict__ gam,
    const float* __restrict__ bet, const float* __restrict__ rmean,
    const float* __restrict__ rvar, float* __restrict__ OUT) {
#if HAS_TCGEN05
    extern __shared__ char smem[];
    const uint32_t sb = smem_to_u32(smem);
    const int tid = threadIdx.x;
    const int wid = tid >> 5;
    const int lid = tid & 31;
    const int m0 = blockIdx.x * 128;
    float* Ssh = (float*)(smem + SM_S);
    float* Tsh = (float*)(smem + SM_T);

    if (wid == 0) {
        asm volatile("tcgen05.alloc.cta_group::1.sync.aligned.shared::cta.b32 [%0], %1;"
                     :: "r"(sb + SM_PTR), "r"(512u) : "memory");
    }
    __syncthreads();
    uint32_t tmem_base;
    asm volatile("ld.shared.b32 %0, [%1];" : "=r"(tmem_base) : "r"(sb + SM_PTR));

    if (tid < 128) {
        float s = gam[tid] * rsqrtf(rvar[tid] + 1e-5f);
        Ssh[tid] = s;
        Tsh[tid] = (bias[tid] - rmean[tid]) * s + bet[tid];
    }

    // B: straight copy of pre-imaged blobs (already swizzled)
    {
        const uint4* bh = (const uint4*)BH;
        const uint4* bl = (const uint4*)BL;
        uint4* sh = (uint4*)(smem + SMB_HI);
        uint4* sl = (uint4*)(smem + SMB_LO);
#pragma unroll
        for (int q = 0; q < 8; q++) {
            int i = q * 256 + tid;
            sh[i] = bh[i];
            sl[i] = bl[i];
        }
    }
    // A: row-major bf16 -> blocked swizzled smem, 16B chunks
    {
#pragma unroll
        for (int q = 0; q < 8; q++) {
            int cid = q * 256 + tid;       // 0..2047
            int r = cid >> 4;
            int k8 = (cid & 15) << 3;
            uint32_t off = ((uint32_t)(k8 >> 6) << 14) | ((uint32_t)(r >> 3) << 10) |
                           ((uint32_t)(r & 7) << 7) | ((uint32_t)(k8 & 63) << 1);
            uint32_t sw = SW128(off);
            int gr = m0 + r;
            uint4 vh = {0u, 0u, 0u, 0u}, vl = {0u, 0u, 0u, 0u};
            if (gr < NN) {
                size_t gaddr = (size_t)gr * DD + k8;
                vh = *(const uint4*)(XH + gaddr);
                vl = *(const uint4*)(XL + gaddr);
            }
            *(uint4*)(smem + SMA_HI + sw) = vh;
            *(uint4*)(smem + SMA_LO + sw) = vl;
        }
    }
    asm volatile("fence.proxy.async.shared::cta;" ::: "memory");
    __syncthreads();

    if (wid == 0) {
        if (elect_one_pred()) MBARRIER_INIT(sb + SM_BAR, 1);
        __syncwarp();
        uint64_t dah = MAKE_SMEM_DESC(sb + SMA_HI);
        uint64_t dal = MAKE_SMEM_DESC(sb + SMA_LO);
        uint64_t dbh = MAKE_SMEM_DESC(sb + SMB_HI);
        uint64_t dbl = MAKE_SMEM_DESC(sb + SMB_LO);
        if (elect_one_pred()) {
#pragma unroll
            for (int s = 0; s < 8; s++) {
                uint64_t off = (uint64_t)((s >> 2) * 1024 + (s & 3) * 2);
                TC_MMA_F16(tmem_base, dah + off, dbh + off, MMA_IDESC128, s > 0 ? 1u : 0u);
                TC_MMA_F16(tmem_base, dah + off, dbl + off, MMA_IDESC128, 1u);
                TC_MMA_F16(tmem_base, dal + off, dbh + off, MMA_IDESC128, 1u);
            }
            asm volatile(
                "tcgen05.commit.cta_group::1.mbarrier::arrive::one.shared::cluster.b64 [%0];"
                :: "r"(sb + SM_BAR) : "memory");
        }
    }

    __syncthreads();
    MBARRIER_WAIT_PARITY(sb + SM_BAR, 0);
    asm volatile("tcgen05.fence::after_thread_sync;" ::: "memory");

    // Epilogue: warps 0-3 cols [0,64), warps 4-7 cols [64,128); rows (w&3)*32+lid
    int gr = m0 + (wid & 3) * 32 + lid;
    int cbase = (wid >> 2) * 64;
#pragma unroll
    for (int cc = 0; cc < 2; cc++) {
        int c0 = cbase + cc * 32;
        uint32_t dreg[32];
        TC_LD_X32(dreg, tmem_base + c0);
        TC_WAIT_LD();
        if (gr < NN) {
#pragma unroll
            for (int j4 = 0; j4 < 8; j4++) {
                int c = c0 + j4 * 4;
                float4 o;
                o.x = fmaxf(fmaf(__uint_as_float(dreg[j4 * 4 + 0]), Ssh[c + 0], Tsh[c + 0]), 0.f);
                o.y = fmaxf(fmaf(__uint_as_float(dreg[j4 * 4 + 1]), Ssh[c + 1], Tsh[c + 1]), 0.f);
                o.z = fmaxf(fmaf(__uint_as_float(dreg[j4 * 4 + 2]), Ssh[c + 2], Tsh[c + 2]), 0.f);
                o.w = fmaxf(fmaf(__uint_as_float(dreg[j4 * 4 + 3]), Ssh[c + 3], Tsh[c + 3]), 0.f);
                *(float4*)(OUT + (size_t)gr * DD + c) = o;
            }
        }
    }
    asm volatile("tcgen05.fence::before_thread_sync;" ::: "memory");
    __syncthreads();
    if (wid == 0) {
        if (elect_one_pred()) MBARRIER_INVAL(sb + SM_BAR);
        asm volatile("tcgen05.dealloc.cta_group::1.sync.aligned.b32 %0, %1;"
                     :: "r"(tmem_base), "r"(512u));
    }
#else
    // SIMT fallback (baseline compute_103 pass only)
    extern __shared__ char smem[];
    float* Ssh = (float*)(smem + SM_S);
    float* Tsh = (float*)(smem + SM_T);
    const int tid = threadIdx.x;
    const int m0 = blockIdx.x * 128;
    if (tid < 128) {
        float s = gam[tid] * rsqrtf(rvar[tid] + 1e-5f);
        Ssh[tid] = s;
        Tsh[tid] = (bias[tid] - rmean[tid]) * s + bet[tid];
    }
    __syncthreads();
    int gr = m0 + tid;
    if (tid < 128 && gr < NN) {
        float a[DD];
#pragma unroll 8
        for (int k = 0; k < DD; k++)
            a[k] = __bfloat162float(XH[(size_t)gr * DD + k]) +
                   __bfloat162float(XL[(size_t)gr * DD + k]);
        for (int n = 0; n < DD; n++) {
            float acc = 0.f;
#pragma unroll 8
            for (int k = 0; k < DD; k++) {
                uint32_t off = ((uint32_t)(k >> 6) << 14) | ((uint32_t)(n >> 3) << 10) |
                               ((uint32_t)(n & 7) << 7) | ((uint32_t)(k & 63) << 1);
                uint32_t sw = SW128(off);
                float wv = __bfloat162float(*(const __nv_bfloat16*)((const char*)BH + sw)) +
                           __bfloat162float(*(const __nv_bfloat16*)((const char*)BL + sw));
                acc = fmaf(a[k], wv, acc);
            }
            OUT[(size_t)gr * DD + n] = fmaxf(fmaf(acc, Ssh[n], Tsh[n]), 0.f);
        }
    }
#endif
}

// ---------------------------------------------------------------------------
// Final (tcgen05): out = 0.5*((h2@wp + bp) + relu(BN(xin2@w2 + b2)))
// D1 (tmem col 0)  = xin2 @ w2  (N=40, bf16x3)
// D2 (tmem col 64) = h2   @ wp  (N=40, bf16x3)
// ---------------------------------------------------------------------------
#define F_PTR 0
#define F_BAR 8
#define F_AXH 1024
#define F_AXL (F_AXH + 32768)
#define F_AHH (F_AXL + 32768)
#define F_AHL (F_AHH + 32768)
#define F_BW2H (F_AHL + 32768)            // 132096, 1024-aligned
#define F_BW2L (F_BW2H + 10240)
#define F_BWPH (F_BW2L + 10240)
#define F_BWPL (F_BWPH + 10240)
#define F_S2  (F_BWPL + 10240)            // 173056
#define F_T2  (F_S2 + 160)
#define F_BP  (F_T2 + 160)
#define F_ZB  (F_BP + 160)                // 173536, 128*40*4 = 20480
#define FINAL_SMEM (F_ZB + 20480)

__global__ __launch_bounds__(256) __cluster_dims__(1, 1, 1) void final_mma(
    const float* __restrict__ H2,
    const __nv_bfloat16* __restrict__ XH, const __nv_bfloat16* __restrict__ XL,
    const __nv_bfloat16* __restrict__ W2H, const __nv_bfloat16* __restrict__ W2L,
    const __nv_bfloat16* __restrict__ WPH, const __nv_bfloat16* __restrict__ WPL,
    const float* __restrict__ b2, const float* __restrict__ g2,
    const float* __restrict__ be2, const float* __restrict__ rm2,
    const float* __restrict__ rv2, const float* __restrict__ bp,
    float* __restrict__ OUT) {
#if HAS_TCGEN05
    extern __shared__ char smem[];
    const uint32_t sb = smem_to_u32(smem);
    const int tid = threadIdx.x;
    const int wid = tid >> 5;
    const int lid = tid & 31;
    const int m0 = blockIdx.x * 128;
    float* S2 = (float*)(smem + F_S2);
    float* T2 = (float*)(smem + F_T2);
    float* BP = (float*)(smem + F_BP);
    float* ZB = (float*)(smem + F_ZB);

    if (wid == 0) {
        asm volatile("tcgen05.alloc.cta_group::1.sync.aligned.shared::cta.b32 [%0], %1;"
                     :: "r"(sb + F_PTR), "r"(512u) : "memory");
    }
    __syncthreads();
    uint32_t tmem_base;
    asm volatile("ld.shared.b32 %0, [%1];" : "=r"(tmem_base) : "r"(sb + F_PTR));

    if (tid < 40) {
        float s = g2[tid] * rsqrtf(rv2[tid] + 1e-5f);
        S2[tid] = s;
        T2[tid] = (b2[tid] - rm2[tid]) * s + be2[tid];
        BP[tid] = bp[tid];
    }

    // B blobs: 640 uint4 each
    {
        const uint4* s0 = (const uint4*)W2H;
        const uint4* s1 = (const uint4*)W2L;
        const uint4* s2 = (const uint4*)WPH;
        const uint4* s3 = (const uint4*)WPL;
        uint4* d0 = (uint4*)(smem + F_BW2H);
        uint4* d1 = (uint4*)(smem + F_BW2L);
        uint4* d2 = (uint4*)(smem + F_BWPH);
        uint4* d3 = (uint4*)(smem + F_BWPL);
        for (int i = tid; i < 640; i += 256) {
            d0[i] = s0[i]; d1[i] = s1[i]; d2[i] = s2[i]; d3[i] = s3[i];
        }
    }
    // xin2 A tiles: bf16 row-major -> swizzled images
    {
#pragma unroll
        for (int q = 0; q < 8; q++) {
            int cid = q * 256 + tid;
            int r = cid >> 4;
            int k8 = (cid & 15) << 3;
            uint32_t off = ((uint32_t)(k8 >> 6) << 14) | ((uint32_t)(r >> 3) << 10) |
                           ((uint32_t)(r & 7) << 7) | ((uint32_t)(k8 & 63) << 1);
            uint32_t sw = SW128(off);
            int gr = m0 + r;
            uint4 vh = {0u, 0u, 0u, 0u}, vl = {0u, 0u, 0u, 0u};
            if (gr < NN) {
                size_t gaddr = (size_t)gr * DD + k8;
                vh = *(const uint4*)(XH + gaddr);
                vl = *(const uint4*)(XL + gaddr);
            }
            *(uint4*)(smem + F_AXH + sw) = vh;
            *(uint4*)(smem + F_AXL + sw) = vl;
        }
    }
    // h2 A tiles: f32 -> bf16 hi/lo split on the fly (4-elem = 8B chunks)
    {
#pragma unroll
        for (int q = 0; q < 16; q++) {
            int cid = q * 256 + tid;        // 0..4095
            int r = cid >> 5;
            int k4 = (cid & 31) << 2;
            uint32_t off = ((uint32_t)(k4 >> 6) << 14) | ((uint32_t)(r >> 3) << 10) |
                           ((uint32_t)(r & 7) << 7) | ((uint32_t)(k4 & 63) << 1);
            uint32_t sw = SW128(off);
            int gr = m0 + r;
            union { __nv_bfloat16 b[4]; uint64_t u; } ph, pl;
            ph.u = 0; pl.u = 0;
            if (gr < NN) {
                float4 v = *(const float4*)(H2 + (size_t)gr * DD + k4);
                float vv[4] = {v.x, v.y, v.z, v.w};
#pragma unroll
                for (int j = 0; j < 4; j++) {
                    __nv_bfloat16 h = __float2bfloat16(vv[j]);
                    ph.b[j] = h;
                    pl.b[j] = __float2bfloat16(vv[j] - __bfloat162float(h));
                }
            }
            *(uint64_t*)(smem + F_AHH + sw) = ph.u;
            *(uint64_t*)(smem + F_AHL + sw) = pl.u;
        }
    }
    asm volatile("fence.proxy.async.shared::cta;" ::: "memory");
    __syncthreads();

    if (wid == 0) {
        if (elect_one_pred()) MBARRIER_INIT(sb + F_BAR, 1);
        __syncwarp();
        uint64_t daxh = MAKE_SMEM_DESC(sb + F_AXH);
        uint64_t daxl = MAKE_SMEM_DESC(sb + F_AXL);
        uint64_t dahh = MAKE_SMEM_DESC(sb + F_AHH);
        uint64_t dahl = MAKE_SMEM_DESC(sb + F_AHL);
        uint64_t dw2h = MAKE_SMEM_DESC(sb + F_BW2H);
        uint64_t dw2l = MAKE_SMEM_DESC(sb + F_BW2L);
        uint64_t dwph = MAKE_SMEM_DESC(sb + F_BWPH);
        uint64_t dwpl = MAKE_SMEM_DESC(sb + F_BWPL);
        if (elect_one_pred()) {
#pragma unroll
            for (int s = 0; s < 8; s++) {
                uint64_t offA = (uint64_t)((s >> 2) * 1024 + (s & 3) * 2);
                uint64_t offB = (uint64_t)((s >> 2) * 320 + (s & 3) * 2);
                uint32_t en0 = s > 0 ? 1u : 0u;
                // D1 = xin2 @ w2
                TC_MMA_F16(tmem_base, daxh + offA, dw2h + offB, MMA_IDESC40, en0);
                TC_MMA_F16(tmem_base, daxh + offA, dw2l + offB, MMA_IDESC40, 1u);
                TC_MMA_F16(tmem_base, daxl + offA, dw2h + offB, MMA_IDESC40, 1u);
                // D2 = h2 @ wp
                TC_MMA_F16(tmem_base + 64, dahh + offA, dwph + offB, MMA_IDESC40, en0);
                TC_MMA_F16(tmem_base + 64, dahh + offA, dwpl + offB, MMA_IDESC40, 1u);
                TC_MMA_F16(tmem_base + 64, dahl + offA, dwph + offB, MMA_IDESC40, 1u);
            }
            asm volatile(
                "tcgen05.commit.cta_group::1.mbarrier::arrive::one.shared::cluster.b64 [%0];"
                :: "r"(sb + F_BAR) : "memory");
        }
    }

    __syncthreads();
    MBARRIER_WAIT_PARITY(sb + F_BAR, 0);
    asm volatile("tcgen05.fence::after_thread_sync;" ::: "memory");

    int row = (wid & 3) * 32 + lid;      // 0..127 within tile
    // wg1 (warps 4-7): D2 = h2@wp, + bp -> ZB
    if (wid >= 4) {
        uint32_t d[40];
        TC_LD_X32(d, tmem_base + 64);
        TC_LD_X8(d + 32, tmem_base + 96);
        TC_WAIT_LD();
#pragma unroll
        for (int c = 0; c < 40; c++)
            ZB[row * 40 + c] = __uint_as_float(d[c]) + BP[c];
    }
    __syncthreads();
    // wg0 (warps 0-3): D1 = xin2@w2, BN+relu, combine, store
    if (wid < 4) {
        uint32_t d[40];
        TC_LD_X32(d, tmem_base);
        TC_LD_X8(d + 32, tmem_base + 32);
        TC_WAIT_LD();
        int gr = m0 + row;
        if (gr < NN) {
#pragma unroll
            for (int c4 = 0; c4 < 40; c4 += 4) {
                float4 o;
                float h0 = fmaxf(fmaf(__uint_as_float(d[c4 + 0]), S2[c4 + 0], T2[c4 + 0]), 0.f);
                float h1 = fmaxf(fmaf(__uint_as_float(d[c4 + 1]), S2[c4 + 1], T2[c4 + 1]), 0.f);
                float h2v = fmaxf(fmaf(__uint_as_float(d[c4 + 2]), S2[c4 + 2], T2[c4 + 2]), 0.f);
                float h3 = fmaxf(fmaf(__uint_as_float(d[c4 + 3]), S2[c4 + 3], T2[c4 + 3]), 0.f);
                o.x = 0.5f * (ZB[row * 40 + c4 + 0] + h0);
                o.y = 0.5f * (ZB[row * 40 + c4 + 1] + h1);
                o.z = 0.5f * (ZB[row * 40 + c4 + 2] + h2v);
                o.w = 0.5f * (ZB[row * 40 + c4 + 3] + h3);
                *(float4*)(OUT + (size_t)gr * CC + c4) = o;
            }
        }
    }
    asm volatile("tcgen05.fence::before_thread_sync;" ::: "memory");
    __syncthreads();
    if (wid == 0) {
        if (elect_one_pred()) MBARRIER_INVAL(sb + F_BAR);
        asm volatile("tcgen05.dealloc.cta_group::1.sync.aligned.b32 %0, %1;"
                     :: "r"(tmem_base), "r"(512u));
    }
#else
    // SIMT fallback (baseline compute_103 pass only)
    const int tid = threadIdx.x;
    const int m0 = blockIdx.x * 128;
    int gr = m0 + tid;
    if (tid < 128 && gr < NN) {
        for (int c = 0; c < CC; c++) {
            float s = g2[c] * rsqrtf(rv2[c] + 1e-5f);
            float t = (b2[c] - rm2[c]) * s + be2[c];
            float a1 = 0.f, a2 = 0.f;
            for (int k = 0; k < DD; k++) {
                uint32_t off = (uint32_t)(k >> 6) * 5120u + ((uint32_t)(c >> 3) << 10) |
                               ((uint32_t)(c & 7) << 7) | ((uint32_t)(k & 63) << 1);
                uint32_t sw = SW128(off);
                float w2v = __bfloat162float(*(const __nv_bfloat16*)((const char*)W2H + sw)) +
                            __bfloat162float(*(const __nv_bfloat16*)((const char*)W2L + sw));
                float wpv = __bfloat162float(*(const __nv_bfloat16*)((const char*)WPH + sw)) +
                            __bfloat162float(*(const __nv_bfloat16*)((const char*)WPL + sw));
                float xk = __bfloat162float(XH[(size_t)gr * DD + k]) +
                           __bfloat162float(XL[(size_t)gr * DD + k]);
                a1 = fmaf(xk, w2v, a1);
                a2 = fmaf(H2[(size_t)gr * DD + k], wpv, a2);
            }
            OUT[(size_t)gr * CC + c] =
                0.5f * ((a2 + bp[c]) + fmaxf(fmaf(a1, s, t), 0.f));
        }
    }
#endif
}

// ---------------------------------------------------------------------------
extern "C" void kernel_launch(void* const* d_in, const int* in_sizes, int n_in,
                              void* d_out, int out_size) {
    const float* h    = (const float*)d_in[0];
    const int*   esrc = (const int*)d_in[1];
    const int*   edst = (const int*)d_in[2];
    const float* mask = (const float*)d_in[3];
    const float* w0 = (const float*)d_in[4];
    const float* b0 = (const float*)d_in[5];
    const float* g0 = (const float*)d_in[6];
    const float* be0 = (const float*)d_in[7];
    const float* rm0 = (const float*)d_in[8];
    const float* rv0 = (const float*)d_in[9];
    const float* w1 = (const float*)d_in[10];
    const float* b1 = (const float*)d_in[11];
    const float* g1 = (const float*)d_in[12];
    const float* be1 = (const float*)d_in[13];
    const float* rm1 = (const float*)d_in[14];
    const float* rv1 = (const float*)d_in[15];
    const float* w2 = (const float*)d_in[16];
    const float* b2 = (const float*)d_in[17];
    const float* g2 = (const float*)d_in[18];
    const float* be2 = (const float*)d_in[19];
    const float* rm2 = (const float*)d_in[20];
    const float* rv2 = (const float*)d_in[21];
    const float* wp = (const float*)d_in[22];
    const float* bp = (const float*)d_in[23];
    float* out = (float*)d_out;

    float *h1b, *h2b, *dinv, *cm;
    __nv_bfloat16 *xh, *xl, *w0h, *w0l, *w1h, *w1l, *w2h, *w2l, *wph, *wpl;
    int *cnt, *cursor, *rowptr, *bsum, *csrc;
    cudaGetSymbolAddress((void**)&h1b, g_h1);
    cudaGetSymbolAddress((void**)&h2b, g_h2);
    cudaGetSymbolAddress((void**)&xh, g_xh);
    cudaGetSymbolAddress((void**)&xl, g_xl);
    cudaGetSymbolAddress((void**)&w0h, g_w0hi);
    cudaGetSymbolAddress((void**)&w0l, g_w0lo);
    cudaGetSymbolAddress((void**)&w1h, g_w1hi);
    cudaGetSymbolAddress((void**)&w1l, g_w1lo);
    cudaGetSymbolAddress((void**)&w2h, g_w2hi);
    cudaGetSymbolAddress((void**)&w2l, g_w2lo);
    cudaGetSymbolAddress((void**)&wph, g_wphi);
    cudaGetSymbolAddress((void**)&wpl, g_wplo);
    cudaGetSymbolAddress((void**)&dinv, g_dinv);
    cudaGetSymbolAddress((void**)&cnt, g_cnt);
    cudaGetSymbolAddress((void**)&cursor, g_cursor);
    cudaGetSymbolAddress((void**)&rowptr, g_rowptr);
    cudaGetSymbolAddress((void**)&bsum, g_bsum);
    cudaGetSymbolAddress((void**)&csrc, g_csrc);
    cudaGetSymbolAddress((void**)&cm, g_cm);

    cudaFuncSetAttribute(gin_gemm_mma, cudaFuncAttributeMaxDynamicSharedMemorySize,
                         GEMM_SMEM);
    cudaFuncSetAttribute(final_mma, cudaFuncAttributeMaxDynamicSharedMemorySize,
                         FINAL_SMEM);

    const int mmaBlocks = (NN + 127) / 128;   // 391
    const int aggBlocks = (NN * 32 + 255) / 256;

    // CSR build + weight pre-imaging (fused)
    cudaMemsetAsync(cnt, 0, NN * sizeof(int));
    prep_kernel<<<PREP_BLKS, 256>>>(edst, cnt, w0, w0h, w0l, w1, w1h, w1l,
                                    w2, w2h, w2l, wp, wph, wpl);
    blocksum_kernel<<<NB, 1024>>>(cnt, bsum);
    scan_bsum_kernel<<<1, 32>>>(bsum);
    scan_write_kernel<<<NB, 1024>>>(cnt, bsum, rowptr, cursor, dinv);
    scatter_kernel<<<(EE + 255) / 256, 256>>>(esrc, edst, mask, cursor, csrc, cm);

    // Layer 0
    agg_xin_bf16_kernel<<<aggBlocks, 256>>>(h, rowptr, csrc, cm, dinv, xh, xl);
    gin_gemm_mma<<<mmaBlocks, 256, GEMM_SMEM>>>(xh, xl, w0h, w0l,
                                                b0, g0, be0, rm0, rv0, h1b);

    // Layer 1
    agg_xin_bf16_kernel<<<aggBlocks, 256>>>(h1b, rowptr, csrc, cm, dinv, xh, xl);
    gin_gemm_mma<<<mmaBlocks, 256, GEMM_SMEM>>>(xh, xl, w1h, w1l,
                                                b1, g1, be1, rm1, rv1, h2b);

    // Layer 2 aggregation + fused final (both GEMMs on tensor cores)
    agg_xin_bf16_kernel<<<aggBlocks, 256>>>(h2b, rowptr, csrc, cm, dinv, xh, xl);
    final_mma<<<mmaBlocks, 256, FINAL_SMEM>>>(h2b, xh, xl, w2h, w2l, wph, wpl,
                                              b2, g2, be2, rm2, rv2, bp, out);
}